// round 11
// baseline (speedup 1.0000x reference)
#include <cuda_runtime.h>
#include <cuda_fp16.h>
#include <math.h>
#include <stdint.h>

// ---------------------------------------------------------------------------
// DiT block. Round 11: R9 numerics (single fp16 both sides, fp32 acc).
// Changes: cross-attn K|V GEMM merged into the qkv launch (fills its wave
// tail); ln_mod on 128-thread blocks. GEMM loop = R9 2-stage (proven best).
// ---------------------------------------------------------------------------

#define Bsz   8
#define Ntok  1024
#define Hdim  1152
#define NHead 16
#define HeadD 72
#define CtxD  768
#define CtxT  77
#define MlpD  4608
#define Mrows (Bsz * Ntok)     // 8192
#define Crows (Bsz * CtxT)     // 616
#define ModW  (6 * Hdim)       // 6912
#define KVW   (2 * Hdim)       // 2304

typedef __half  f16;
typedef __half2 f162;

// ------------------------- scratch (no allocations) ------------------------
__device__ float g_mod [Bsz * ModW];
__device__ float g_xb  [Mrows * Hdim];

__device__ f16 g_ln  [Mrows * Hdim];
__device__ f16 g_at  [Mrows * Hdim];
__device__ f16 g_xbh [Mrows * Hdim];
__device__ f16 g_qkv [Mrows * 3 * Hdim];
__device__ f16 g_kv  [Crows * KVW];
__device__ f16 g_hid [Mrows * MlpD];
__device__ f16 g_c   [Crows * CtxD];
__device__ f16 g_wqkv[3 * Hdim * Hdim];
__device__ f16 g_wpr [Hdim * Hdim];
__device__ f16 g_wq  [Hdim * Hdim];
__device__ f16 g_wkv [KVW * CtxD];
__device__ f16 g_wo  [Hdim * Hdim];
__device__ f16 g_w1  [MlpD * Hdim];
__device__ f16 g_w2  [Hdim * MlpD];

// ------------------------------ helpers ------------------------------------
__device__ __forceinline__ float ex2(float x) {
  float y; asm("ex2.approx.f32 %0, %1;" : "=f"(y) : "f"(x)); return y;
}
__device__ __forceinline__ uint32_t pack_f16x2(float lo, float hi) {
  uint32_t d;
  asm("cvt.rn.f16x2.f32 %0, %1, %2;" : "=r"(d) : "f"(hi), "f"(lo));
  return d;
}

// -------------------- fused weight/context conversion ----------------------
struct CvtJobs {
  const float* src[9];
  f16* dst[9];
  int n[9];
};

__global__ __launch_bounds__(256) void cvt_all_kernel(CvtJobs J) {
  int t = blockIdx.y;
  int i = (blockIdx.x * 256 + threadIdx.x) * 4;
  if (i >= J.n[t]) return;
  float4 v = *(const float4*)(J.src[t] + i);
  f16* d = J.dst[t];
  *(f162*)(d + i)     = __floats2half2_rn(v.x, v.y);
  *(f162*)(d + i + 2) = __floats2half2_rn(v.z, v.w);
}

// --------------------------- adaLN modulation ------------------------------
__global__ __launch_bounds__(128) void ada_kernel(
    const float* __restrict__ t_emb, const float* __restrict__ ada_w,
    const float* __restrict__ ada_b, float* __restrict__ mod) {
  __shared__ float se[Bsz * Hdim];
  int tid = threadIdx.x;
  for (int i = tid; i < Bsz * Hdim; i += 128) {
    float v = t_emb[i];
    se[i] = v / (1.f + __expf(-v));
  }
  __syncthreads();
  int j = blockIdx.x * 128 + tid;
  const float* w = ada_w + (size_t)j * Hdim;
  float acc[Bsz];
#pragma unroll
  for (int b = 0; b < Bsz; b++) acc[b] = 0.f;
  for (int k = 0; k < Hdim; k += 4) {
    float4 wv = *(const float4*)(w + k);
#pragma unroll
    for (int b = 0; b < Bsz; b++) {
      const float* s = se + b * Hdim + k;
      acc[b] += wv.x * s[0] + wv.y * s[1] + wv.z * s[2] + wv.w * s[3];
    }
  }
  float bb = ada_b[j];
#pragma unroll
  for (int b = 0; b < Bsz; b++) mod[b * ModW + j] = acc[b] + bb;
}

// ----------------- LayerNorm + modulate -> fp16 (128 thr) -------------------
__global__ __launch_bounds__(128) void ln_mod_kernel(
    const float* __restrict__ x, const float* __restrict__ mod,
    int sh_off, int sc_off, f16* __restrict__ o16) {
  int row = blockIdx.x;
  int b = row >> 10;
  const float* xr = x + (size_t)row * Hdim;
  int tid = threadIdx.x;
  float s = 0.f, ss = 0.f;
  for (int i = tid; i < Hdim; i += 128) {
    float v = xr[i];
    s += v; ss += v * v;
  }
#pragma unroll
  for (int o = 16; o > 0; o >>= 1) {
    s  += __shfl_xor_sync(0xffffffffu, s, o);
    ss += __shfl_xor_sync(0xffffffffu, ss, o);
  }
  __shared__ float rs[4], rss[4], stat[2];
  int w = tid >> 5;
  if ((tid & 31) == 0) { rs[w] = s; rss[w] = ss; }
  __syncthreads();
  if (tid == 0) {
    float S = rs[0] + rs[1] + rs[2] + rs[3];
    float SS = rss[0] + rss[1] + rss[2] + rss[3];
    float mu = S * (1.f / Hdim);
    float var = SS * (1.f / Hdim) - mu * mu;
    stat[0] = mu;
    stat[1] = rsqrtf(var + 1e-6f);
  }
  __syncthreads();
  float mu = stat[0], rstd = stat[1];
  const float* sh = mod + b * ModW + sh_off * Hdim;
  const float* sc = mod + b * ModW + sc_off * Hdim;
  f16* o = o16 + (size_t)row * Hdim;
  for (int i = tid; i < Hdim; i += 128)
    o[i] = __float2half((xr[i] - mu) * rstd * (1.f + sc[i]) + sh[i]);
}

// ------------------- tensor-core GEMM (NT, fp16) ----------------------------
__device__ __forceinline__ float gelu_tanh(float v) {
  const float c = 0.7978845608028654f;
  return 0.5f * v * (1.f + tanhf(c * (v + 0.044715f * v * v * v)));
}

#define EPI_BIAS    0
#define EPI_GELU    1
#define EPI_RESGATE 2

__device__ __forceinline__ void mma_f16(float c[4], const uint32_t a[4],
                                        const uint32_t b[2]) {
  asm volatile(
      "mma.sync.aligned.m16n8k16.row.col.f32.f16.f16.f32 "
      "{%0,%1,%2,%3}, {%4,%5,%6,%7}, {%8,%9}, {%0,%1,%2,%3};"
      : "+f"(c[0]), "+f"(c[1]), "+f"(c[2]), "+f"(c[3])
      : "r"(a[0]), "r"(a[1]), "r"(a[2]), "r"(a[3]), "r"(b[0]), "r"(b[1]));
}

__device__ __forceinline__ void ldsm4(uint32_t r[4], uint32_t addr) {
  asm volatile("ldmatrix.sync.aligned.m8n8.x4.shared.b16 {%0,%1,%2,%3}, [%4];"
               : "=r"(r[0]), "=r"(r[1]), "=r"(r[2]), "=r"(r[3]) : "r"(addr));
}
__device__ __forceinline__ void ldsm4t(uint32_t r[4], uint32_t addr) {
  asm volatile(
      "ldmatrix.sync.aligned.m8n8.x4.trans.shared.b16 {%0,%1,%2,%3}, [%4];"
      : "=r"(r[0]), "=r"(r[1]), "=r"(r[2]), "=r"(r[3]) : "r"(addr));
}

__device__ __forceinline__ void cp16(uint32_t dst, const void* src, bool p) {
  int sz = p ? 16 : 0;
  asm volatile("cp.async.cg.shared.global [%0], [%1], 16, %2;\n"
               :: "r"(dst), "l"(src), "r"(sz));
}

// K-tile 64: plane = 128 rows x 144B (128B data + 16B pad). 2 stages.
#define PL_B    18432
#define STAGE_B (2 * PL_B)       // A, B = 36864
#define GSMEM   (2 * STAGE_B)    // 73728

// Shared GEMM body (R9-proven 2-stage pipeline).
template <int EPI, bool OUTF, bool OUTB>
__device__ __forceinline__ void gemm_body(
    const f16* __restrict__ A, const f16* __restrict__ W,
    const float* __restrict__ bias, const float* __restrict__ res,
    const float* __restrict__ gate, float* __restrict__ C,
    f16* __restrict__ C16,
    int M, int N, int K, int bx, int by) {
  extern __shared__ char smc[];
  uint32_t sbase = (uint32_t)__cvta_generic_to_shared(smc);
  int tid = threadIdx.x;
  int warp = tid >> 5, lane = tid & 31;
  int wm = warp & 3, wn = warp >> 2;     // 4 warps M x 2 warps N
  int m0 = by << 7, n0 = bx << 7;

  float acc[2][8][4];
#pragma unroll
  for (int mt = 0; mt < 2; mt++)
#pragma unroll
    for (int nt = 0; nt < 8; nt++)
#pragma unroll
      for (int f = 0; f < 4; f++) acc[mt][nt][f] = 0.f;

  int lq = lane & 7, lb = (lane >> 3) & 1, lh = lane >> 4;
  uint32_t offA[2], offB[4];
#pragma unroll
  for (int mt = 0; mt < 2; mt++)
    offA[mt] = (uint32_t)((wm * 32 + mt * 16 + lq + lb * 8) * 144 + lh * 16);
#pragma unroll
  for (int j = 0; j < 4; j++)
    offB[j] = (uint32_t)(PL_B +
                         (wn * 64 + j * 16 + lq + lh * 8) * 144 + lb * 16);

  const int nk = K >> 6;

  auto issue = [&](int kt, int s) {
    uint32_t st = sbase + s * STAGE_B;
    int k0 = kt << 6;
#pragma unroll
    for (int i = 0; i < 8; i++) {
      int idx = tid + (i << 8);
      int pl = idx >> 10;          // 0=A, 1=B
      int cc = idx & 1023;
      int row = cc >> 3, ch = cc & 7;
      uint32_t d = st + pl * PL_B + row * 144 + ch * 16;
      const f16* src;
      bool ok = true;
      if (pl == 0) {
        int gm = m0 + row;
        ok = gm < M;
        src = A + (size_t)(ok ? gm : 0) * K + k0 + ch * 8;
      } else {
        src = W + (size_t)(n0 + row) * K + k0 + ch * 8;
      }
      cp16(d, src, ok);
    }
    asm volatile("cp.async.commit_group;\n");
  };

  issue(0, 0);
  for (int kt = 0; kt < nk; kt++) {
    int s = kt & 1;
    if (kt + 1 < nk) {
      issue(kt + 1, s ^ 1);
      asm volatile("cp.async.wait_group 1;\n");
    } else {
      asm volatile("cp.async.wait_group 0;\n");
    }
    __syncthreads();

    uint32_t sb = sbase + s * STAGE_B;
#pragma unroll
    for (int ks = 0; ks < 4; ks++) {
      uint32_t a_[2][4];
#pragma unroll
      for (int mt = 0; mt < 2; mt++)
        ldsm4(a_[mt], sb + offA[mt] + ks * 32);
#pragma unroll
      for (int jp = 0; jp < 2; jp++) {
        uint32_t b0[4], b1[4];
        ldsm4(b0, sb + offB[2 * jp]     + ks * 32);
        ldsm4(b1, sb + offB[2 * jp + 1] + ks * 32);
        float (*a0)[4] = acc[0], (*a1)[4] = acc[1];
        int q = 4 * jp;
        mma_f16(a0[q],     a_[0], b0);
        mma_f16(a0[q + 1], a_[0], b0 + 2);
        mma_f16(a1[q],     a_[1], b0);
        mma_f16(a1[q + 1], a_[1], b0 + 2);
        mma_f16(a0[q + 2], a_[0], b1);
        mma_f16(a0[q + 3], a_[0], b1 + 2);
        mma_f16(a1[q + 2], a_[1], b1);
        mma_f16(a1[q + 3], a_[1], b1 + 2);
      }
    }
    __syncthreads();
  }

  int g = lane >> 2, tg = lane & 3;
#pragma unroll
  for (int mt = 0; mt < 2; mt++) {
#pragma unroll
    for (int half = 0; half < 2; half++) {
      int m = m0 + wm * 32 + mt * 16 + g + half * 8;
      if (m >= M) continue;
      int bq = m >> 10;
#pragma unroll
      for (int nt = 0; nt < 8; nt++) {
        int n = n0 + wn * 64 + nt * 8 + tg * 2;
        float v0 = acc[mt][nt][half * 2 + 0];
        float v1 = acc[mt][nt][half * 2 + 1];
        if (bias) { v0 += bias[n]; v1 += bias[n + 1]; }
        if (EPI == EPI_GELU) { v0 = gelu_tanh(v0); v1 = gelu_tanh(v1); }
        if (EPI == EPI_RESGATE) {
          float g0 = 1.f, g1 = 1.f;
          if (gate) { g0 = gate[bq * ModW + n]; g1 = gate[bq * ModW + n + 1]; }
          v0 = res[(size_t)m * N + n] + g0 * v0;
          v1 = res[(size_t)m * N + n + 1] + g1 * v1;
        }
        if (OUTF)
          *(float2*)(C + (size_t)m * N + n) = make_float2(v0, v1);
        if (OUTB)
          *(f162*)(C16 + (size_t)m * N + n) = __floats2half2_rn(v0, v1);
      }
    }
  }
}

template <int EPI, bool OUTF, bool OUTB>
__global__ __launch_bounds__(256, 2) void gemm_tc(
    const f16* __restrict__ A, const f16* __restrict__ W,
    const float* __restrict__ bias, const float* __restrict__ res,
    const float* __restrict__ gate, float* __restrict__ C,
    f16* __restrict__ C16,
    int M, int N, int K) {
  gemm_body<EPI, OUTF, OUTB>(A, W, bias, res, gate, C, C16, M, N, K,
                             blockIdx.x, blockIdx.y);
}

// Merged qkv + cross-attn K|V launch: z=0 -> qkv, z=1 -> kv (18x5 blocks).
__global__ __launch_bounds__(256, 2) void gemm_qkv_kv(
    const float* __restrict__ qkv_b) {
  if (blockIdx.z == 0) {
    gemm_body<EPI_BIAS, false, true>(
        g_ln, g_wqkv, qkv_b, nullptr, nullptr, nullptr, g_qkv,
        Mrows, 3 * Hdim, Hdim, blockIdx.x, blockIdx.y);
  } else {
    if (blockIdx.x >= KVW / 128 || blockIdx.y >= (Crows + 127) / 128) return;
    gemm_body<EPI_BIAS, false, true>(
        g_c, g_wkv, nullptr, nullptr, nullptr, nullptr, g_kv,
        Crows, KVW, CtxD, blockIdx.x, blockIdx.y);
  }
}

// ---------------- tensor-core flash attention (fp16) ------------------------
#define ARB   176
#define APL   (128 * ARB)
#define ATSM  (5 * APL)            // Q + 2 stages x (K,V)

__global__ __launch_bounds__(256) void attn_tc(
    const f16* __restrict__ Q, long long qbs, int ldq,
    const f16* __restrict__ Kp, const f16* __restrict__ Vp,
    long long kbs, int ldk,
    f16* __restrict__ O,
    int kv_len, float sl2e) {
  extern __shared__ char smb[];
  uint32_t sb = (uint32_t)__cvta_generic_to_shared(smb);
  int b = blockIdx.z, h = blockIdx.y;
  int m0 = blockIdx.x * 128;
  int tid = threadIdx.x, warp = tid >> 5, lane = tid & 31;
  int g = lane >> 2, tg = lane & 3;
  int lq = lane & 7, lb = (lane >> 3) & 1, lh = lane >> 4;

  const f16* Qb = Q  + (size_t)b * qbs + (size_t)m0 * ldq + h * HeadD;
  const f16* Kb = Kp + (size_t)b * kbs + h * HeadD;
  const f16* Vb = Vp + (size_t)b * kbs + h * HeadD;

  for (int i = tid; i < 640; i += 256) {
    int p = i >> 7, r = i & 127;
    uint32_t ad = sb + p * APL + r * ARB + 144;
    asm volatile("st.shared.v4.b32 [%0], {%1,%1,%1,%1};" :: "r"(ad), "r"(0));
    asm volatile("st.shared.v4.b32 [%0], {%1,%1,%1,%1};"
                 :: "r"(ad + 16), "r"(0));
  }

  for (int i = tid; i < 1152; i += 256) {
    int r = i / 9, ch = i % 9;
    cp16(sb + r * ARB + ch * 16, Qb + (size_t)r * ldq + ch * 8, true);
  }

  auto loadKV = [&](int j0, int s) {
    uint32_t st = sb + APL + s * 2 * APL;
    for (int i = tid; i < 1152; i += 256) {
      int r = i / 9, ch = i % 9;
      bool ok = (j0 + r) < kv_len;
      int rc = ok ? (j0 + r) : 0;
      size_t off = (size_t)rc * ldk + ch * 8;
      uint32_t d = st + r * ARB + ch * 16;
      cp16(d,       Kb + off, ok);
      cp16(d + APL, Vb + off, ok);
    }
    asm volatile("cp.async.commit_group;\n");
  };

  int iters = (kv_len + 127) >> 7;
  loadKV(0, 0);
  if (iters > 1) loadKV(128, 1);

  float m0r = -1e30f, m1r = -1e30f, ls0 = 0.f, ls1 = 0.f;
  float oacc[9][4];
#pragma unroll
  for (int nt = 0; nt < 9; nt++)
#pragma unroll
    for (int f = 0; f < 4; f++) oacc[nt][f] = 0.f;

  uint32_t offA = (uint32_t)((warp * 16 + lq + lb * 8) * ARB + lh * 16);
  uint32_t offB = (uint32_t)((lq + lh * 8) * ARB + lb * 16);
  uint32_t offV = (uint32_t)((lq + lb * 8) * ARB + lh * 16);

  for (int it = 0; it < iters; it++) {
    if (it + 1 < iters) {
      if (it > 0) loadKV((it + 1) * 128, (it + 1) & 1);
      asm volatile("cp.async.wait_group 1;\n");
    } else {
      asm volatile("cp.async.wait_group 0;\n");
    }
    __syncthreads();

    uint32_t kbse = sb + APL + (it & 1) * 2 * APL;

    float sa[16][4];
#pragma unroll
    for (int j = 0; j < 16; j++)
#pragma unroll
      for (int f = 0; f < 4; f++) sa[j][f] = 0.f;

#pragma unroll
    for (int ks = 0; ks < 5; ks++) {
      uint32_t a_[4];
      ldsm4(a_, sb + offA + ks * 32);
#pragma unroll
      for (int ntp = 0; ntp < 4; ntp++) {
        uint32_t b0[4], b1[4];
        ldsm4(b0, kbse + offB + (2 * ntp) * 16 * ARB + ks * 32);
        ldsm4(b1, kbse + offB + (2 * ntp + 1) * 16 * ARB + ks * 32);
        int q = 4 * ntp;
        mma_f16(sa[q],     a_, b0);
        mma_f16(sa[q + 1], a_, b0 + 2);
        mma_f16(sa[q + 2], a_, b1);
        mma_f16(sa[q + 3], a_, b1 + 2);
      }
    }

    int j0 = it * 128;
    bool msk = (j0 + 128) > kv_len;
    float mx0 = -1e30f, mx1 = -1e30f;
#pragma unroll
    for (int j = 0; j < 16; j++) {
#pragma unroll
      for (int e = 0; e < 4; e++) {
        float v = sa[j][e] * sl2e;
        if (msk) {
          int col = j * 8 + 2 * tg + (e & 1);
          if (j0 + col >= kv_len) v = -1e30f;
        }
        sa[j][e] = v;
      }
      mx0 = fmaxf(mx0, fmaxf(sa[j][0], sa[j][1]));
      mx1 = fmaxf(mx1, fmaxf(sa[j][2], sa[j][3]));
    }
    mx0 = fmaxf(mx0, __shfl_xor_sync(0xffffffffu, mx0, 1));
    mx0 = fmaxf(mx0, __shfl_xor_sync(0xffffffffu, mx0, 2));
    mx1 = fmaxf(mx1, __shfl_xor_sync(0xffffffffu, mx1, 1));
    mx1 = fmaxf(mx1, __shfl_xor_sync(0xffffffffu, mx1, 2));
    float mn0 = fmaxf(m0r, mx0), mn1 = fmaxf(m1r, mx1);
    float al0 = ex2(m0r - mn0), al1 = ex2(m1r - mn1);
    m0r = mn0; m1r = mn1;

    float s0 = 0.f, s1 = 0.f;
#pragma unroll
    for (int j = 0; j < 16; j++) {
      float p0 = ex2(sa[j][0] - mn0), p1 = ex2(sa[j][1] - mn0);
      float p2 = ex2(sa[j][2] - mn1), p3 = ex2(sa[j][3] - mn1);
      sa[j][0] = p0; sa[j][1] = p1; sa[j][2] = p2; sa[j][3] = p3;
      s0 += p0 + p1; s1 += p2 + p3;
    }
    s0 += __shfl_xor_sync(0xffffffffu, s0, 1);
    s0 += __shfl_xor_sync(0xffffffffu, s0, 2);
    s1 += __shfl_xor_sync(0xffffffffu, s1, 1);
    s1 += __shfl_xor_sync(0xffffffffu, s1, 2);
    ls0 = ls0 * al0 + s0;
    ls1 = ls1 * al1 + s1;
#pragma unroll
    for (int nt = 0; nt < 9; nt++) {
      oacc[nt][0] *= al0; oacc[nt][1] *= al0;
      oacc[nt][2] *= al1; oacc[nt][3] *= al1;
    }

    uint32_t vbse = kbse + APL;
#pragma unroll
    for (int kc = 0; kc < 8; kc++) {
      uint32_t pa[4];
#pragma unroll
      for (int jj = 0; jj < 2; jj++) {
        int j = 2 * kc + jj;
        pa[2 * jj]     = pack_f16x2(sa[j][0], sa[j][1]);
        pa[2 * jj + 1] = pack_f16x2(sa[j][2], sa[j][3]);
      }
#pragma unroll
      for (int npp = 0; npp < 2; npp++) {
        int np0 = 2 * npp, np1 = 2 * npp + 1;
        uint32_t v0[4], v1[4];
        ldsm4t(v0, vbse + offV + kc * 16 * ARB + np0 * 32);
        ldsm4t(v1, vbse + offV + kc * 16 * ARB + np1 * 32);
        mma_f16(oacc[2 * np0],     pa, v0);
        mma_f16(oacc[2 * np0 + 1], pa, v0 + 2);
        mma_f16(oacc[2 * np1],     pa, v1);
        mma_f16(oacc[2 * np1 + 1], pa, v1 + 2);
      }
      {
        uint32_t v4[4];
        ldsm4t(v4, vbse + offV + kc * 16 * ARB + 4 * 32);
        mma_f16(oacc[8], pa, v4);
      }
    }
    __syncthreads();
  }

  float inv0 = 1.f / ls0, inv1 = 1.f / ls1;
  int r0 = m0 + warp * 16 + g, r1 = r0 + 8;
  size_t base0 = ((size_t)b * Ntok + r0) * Hdim + h * HeadD;
  size_t base1 = ((size_t)b * Ntok + r1) * Hdim + h * HeadD;
#pragma unroll
  for (int nt = 0; nt < 9; nt++) {
    int col = nt * 8 + 2 * tg;
    *(f162*)(O + base0 + col) =
        __floats2half2_rn(oacc[nt][0] * inv0, oacc[nt][1] * inv0);
    *(f162*)(O + base1 + col) =
        __floats2half2_rn(oacc[nt][2] * inv1, oacc[nt][3] * inv1);
  }
}

// ------------------------------ launcher -----------------------------------
static float* sym_f(const void* s) { void* p; cudaGetSymbolAddress(&p, s); return (float*)p; }
static f16*   sym_h(const void* s) { void* p; cudaGetSymbolAddress(&p, s); return (f16*)p; }

extern "C" void kernel_launch(void* const* d_in, const int* in_sizes, int n_in,
                              void* d_out, int out_size) {
  (void)in_sizes; (void)n_in; (void)out_size;
  const float* x        = (const float*)d_in[0];
  const float* c        = (const float*)d_in[1];
  const float* t_emb    = (const float*)d_in[2];
  const float* qkv_w    = (const float*)d_in[3];
  const float* qkv_b    = (const float*)d_in[4];
  const float* proj_w   = (const float*)d_in[5];
  const float* proj_b   = (const float*)d_in[6];
  const float* to_q_w   = (const float*)d_in[7];
  const float* to_k_w   = (const float*)d_in[8];
  const float* to_v_w   = (const float*)d_in[9];
  const float* to_out_w = (const float*)d_in[10];
  const float* to_out_b = (const float*)d_in[11];
  const float* mlp_w1   = (const float*)d_in[12];
  const float* mlp_b1   = (const float*)d_in[13];
  const float* mlp_w2   = (const float*)d_in[14];
  const float* mlp_b2   = (const float*)d_in[15];
  const float* ada_w    = (const float*)d_in[16];
  const float* ada_b    = (const float*)d_in[17];
  float* out = (float*)d_out;

  float *mod = sym_f(&g_mod), *xb = sym_f(&g_xb);
  f16 *ln = sym_h(&g_ln), *at = sym_h(&g_at), *xbh = sym_h(&g_xbh);
  f16 *qkv = sym_h(&g_qkv), *kv = sym_h(&g_kv), *hid = sym_h(&g_hid);
  f16 *cc = sym_h(&g_c);
  f16 *wqkv = sym_h(&g_wqkv), *wpr = sym_h(&g_wpr), *wq = sym_h(&g_wq);
  f16 *wkv = sym_h(&g_wkv), *wo = sym_h(&g_wo);
  f16 *w1 = sym_h(&g_w1), *w2 = sym_h(&g_w2);

  cudaFuncSetAttribute(attn_tc,
                       cudaFuncAttributeMaxDynamicSharedMemorySize, ATSM);
  cudaFuncSetAttribute(gemm_qkv_kv,
                       cudaFuncAttributeMaxDynamicSharedMemorySize, GSMEM);
#define SETSM(k) cudaFuncSetAttribute(k, \
    cudaFuncAttributeMaxDynamicSharedMemorySize, GSMEM)
  SETSM((gemm_tc<EPI_BIAS, false, true>));
  SETSM((gemm_tc<EPI_GELU, false, true>));
  SETSM((gemm_tc<EPI_RESGATE, true, true>));
  SETSM((gemm_tc<EPI_RESGATE, true, false>));
#undef SETSM

  const float sl2e = (1.f / sqrtf((float)HeadD)) * 1.4426950408889634f;

  // conversions: 8 weight tensors + context, all single fp16
  {
    CvtJobs J;
    const float* s[9] = {qkv_w, proj_w, to_q_w, to_k_w, to_v_w,
                         to_out_w, mlp_w1, mlp_w2, c};
    f16* dd[9] = {wqkv, wpr, wq, wkv, wkv + Hdim * CtxD, wo, w1, w2, cc};
    int nn[9] = {3 * Hdim * Hdim, Hdim * Hdim, Hdim * Hdim, Hdim * CtxD,
                 Hdim * CtxD, Hdim * Hdim, MlpD * Hdim, Hdim * MlpD,
                 Crows * CtxD};
    for (int i = 0; i < 9; i++) { J.src[i] = s[i]; J.dst[i] = dd[i];
                                  J.n[i] = nn[i]; }
    dim3 g((MlpD * Hdim / 4 + 255) / 256, 9);
    cvt_all_kernel<<<g, 256>>>(J);
  }
  ada_kernel<<<ModW / 128, 128>>>(t_emb, ada_w, ada_b, mod);
  ln_mod_kernel<<<Mrows, 128>>>(x, mod, 0, 1, ln);
  // qkv + cross-attn K|V (merged launch)
  {
    dim3 g(3 * Hdim / 128, Mrows / 128, 2);
    gemm_qkv_kv<<<g, 256, GSMEM>>>(qkv_b);
  }
  // self-attention
  {
    dim3 g(Ntok / 128, NHead, Bsz);
    attn_tc<<<g, 256, ATSM>>>(
        qkv, (long long)Ntok * 3 * Hdim, 3 * Hdim,
        qkv + Hdim, qkv + 2 * Hdim, (long long)Ntok * 3 * Hdim, 3 * Hdim,
        at, Ntok, sl2e);
  }
  // proj + gated residual; cross-attn Q
  {
    dim3 g(Hdim / 128, Mrows / 128);
    gemm_tc<EPI_RESGATE, true, true><<<g, 256, GSMEM>>>(
        at, wpr, proj_b, x, mod + 2 * Hdim,
        xb, xbh, Mrows, Hdim, Hdim);
    gemm_tc<EPI_BIAS, false, true><<<g, 256, GSMEM>>>(
        xbh, wq, nullptr, nullptr, nullptr,
        nullptr, ln, Mrows, Hdim, Hdim);
  }
  // cross-attention (kv was produced by the merged launch above)
  {
    dim3 g(Ntok / 128, NHead, Bsz);
    attn_tc<<<g, 256, ATSM>>>(
        ln, (long long)Ntok * Hdim, Hdim,
        kv, kv + Hdim, (long long)CtxT * KVW, KVW,
        at, CtxT, sl2e);
  }
  // to_out + residual
  {
    dim3 g(Hdim / 128, Mrows / 128);
    gemm_tc<EPI_RESGATE, true, false><<<g, 256, GSMEM>>>(
        at, wo, to_out_b, xb, nullptr,
        xb, nullptr, Mrows, Hdim, Hdim);
  }
  ln_mod_kernel<<<Mrows, 128>>>(xb, mod, 3, 4, ln);
  // MLP
  {
    dim3 g1(MlpD / 128, Mrows / 128);
    gemm_tc<EPI_GELU, false, true><<<g1, 256, GSMEM>>>(
        ln, w1, mlp_b1, nullptr, nullptr,
        nullptr, hid, Mrows, MlpD, Hdim);
    dim3 g2(Hdim / 128, Mrows / 128);
    gemm_tc<EPI_RESGATE, true, false><<<g2, 256, GSMEM>>>(
        hid, w2, mlp_b2, xb, mod + 5 * Hdim,
        out, nullptr, Mrows, Hdim, MlpD);
  }
}

// round 12
// speedup vs baseline: 1.0126x; 1.0126x over previous
#include <cuda_runtime.h>
#include <cuda_fp16.h>
#include <math.h>
#include <stdint.h>

// ---------------------------------------------------------------------------
// DiT block. Round 12: R9 base (single fp16 both sides, fp32 acc, 2-stage
// GEMMs). Attention: k8 tail for HD=72 (drops the zero-padded half k-step,
// bit-identical) + cross-attention templated to an 80-wide KV tile.
// ---------------------------------------------------------------------------

#define Bsz   8
#define Ntok  1024
#define Hdim  1152
#define NHead 16
#define HeadD 72
#define CtxD  768
#define CtxT  77
#define MlpD  4608
#define Mrows (Bsz * Ntok)     // 8192
#define Crows (Bsz * CtxT)     // 616
#define ModW  (6 * Hdim)       // 6912
#define KVW   (2 * Hdim)       // 2304

typedef __half  f16;
typedef __half2 f162;

// ------------------------- scratch (no allocations) ------------------------
__device__ float g_mod [Bsz * ModW];
__device__ float g_xb  [Mrows * Hdim];

__device__ f16 g_ln  [Mrows * Hdim];
__device__ f16 g_at  [Mrows * Hdim];
__device__ f16 g_xbh [Mrows * Hdim];
__device__ f16 g_qkv [Mrows * 3 * Hdim];
__device__ f16 g_kv  [Crows * KVW];
__device__ f16 g_hid [Mrows * MlpD];
__device__ f16 g_c   [Crows * CtxD];
__device__ f16 g_wqkv[3 * Hdim * Hdim];
__device__ f16 g_wpr [Hdim * Hdim];
__device__ f16 g_wq  [Hdim * Hdim];
__device__ f16 g_wkv [KVW * CtxD];
__device__ f16 g_wo  [Hdim * Hdim];
__device__ f16 g_w1  [MlpD * Hdim];
__device__ f16 g_w2  [Hdim * MlpD];

// ------------------------------ helpers ------------------------------------
__device__ __forceinline__ float ex2(float x) {
  float y; asm("ex2.approx.f32 %0, %1;" : "=f"(y) : "f"(x)); return y;
}
__device__ __forceinline__ uint32_t pack_f16x2(float lo, float hi) {
  uint32_t d;
  asm("cvt.rn.f16x2.f32 %0, %1, %2;" : "=r"(d) : "f"(hi), "f"(lo));
  return d;
}

// -------------------- fused weight/context conversion ----------------------
struct CvtJobs {
  const float* src[9];
  f16* dst[9];
  int n[9];
};

__global__ __launch_bounds__(256) void cvt_all_kernel(CvtJobs J) {
  int t = blockIdx.y;
  int i = (blockIdx.x * 256 + threadIdx.x) * 4;
  if (i >= J.n[t]) return;
  float4 v = *(const float4*)(J.src[t] + i);
  f16* d = J.dst[t];
  *(f162*)(d + i)     = __floats2half2_rn(v.x, v.y);
  *(f162*)(d + i + 2) = __floats2half2_rn(v.z, v.w);
}

// --------------------------- adaLN modulation ------------------------------
__global__ __launch_bounds__(128) void ada_kernel(
    const float* __restrict__ t_emb, const float* __restrict__ ada_w,
    const float* __restrict__ ada_b, float* __restrict__ mod) {
  __shared__ float se[Bsz * Hdim];
  int tid = threadIdx.x;
  for (int i = tid; i < Bsz * Hdim; i += 128) {
    float v = t_emb[i];
    se[i] = v / (1.f + __expf(-v));
  }
  __syncthreads();
  int j = blockIdx.x * 128 + tid;
  const float* w = ada_w + (size_t)j * Hdim;
  float acc[Bsz];
#pragma unroll
  for (int b = 0; b < Bsz; b++) acc[b] = 0.f;
  for (int k = 0; k < Hdim; k += 4) {
    float4 wv = *(const float4*)(w + k);
#pragma unroll
    for (int b = 0; b < Bsz; b++) {
      const float* s = se + b * Hdim + k;
      acc[b] += wv.x * s[0] + wv.y * s[1] + wv.z * s[2] + wv.w * s[3];
    }
  }
  float bb = ada_b[j];
#pragma unroll
  for (int b = 0; b < Bsz; b++) mod[b * ModW + j] = acc[b] + bb;
}

// ----------------- LayerNorm + modulate -> fp16 -----------------------------
__global__ __launch_bounds__(256) void ln_mod_kernel(
    const float* __restrict__ x, const float* __restrict__ mod,
    int sh_off, int sc_off, f16* __restrict__ o16) {
  int row = blockIdx.x;
  int b = row >> 10;
  const float* xr = x + (size_t)row * Hdim;
  int tid = threadIdx.x;
  float s = 0.f, ss = 0.f;
  for (int i = tid; i < Hdim; i += 256) {
    float v = xr[i];
    s += v; ss += v * v;
  }
#pragma unroll
  for (int o = 16; o > 0; o >>= 1) {
    s  += __shfl_xor_sync(0xffffffffu, s, o);
    ss += __shfl_xor_sync(0xffffffffu, ss, o);
  }
  __shared__ float rs[8], rss[8], stat[2];
  int w = tid >> 5;
  if ((tid & 31) == 0) { rs[w] = s; rss[w] = ss; }
  __syncthreads();
  if (tid == 0) {
    float S = 0.f, SS = 0.f;
#pragma unroll
    for (int i = 0; i < 8; i++) { S += rs[i]; SS += rss[i]; }
    float mu = S * (1.f / Hdim);
    float var = SS * (1.f / Hdim) - mu * mu;
    stat[0] = mu;
    stat[1] = rsqrtf(var + 1e-6f);
  }
  __syncthreads();
  float mu = stat[0], rstd = stat[1];
  const float* sh = mod + b * ModW + sh_off * Hdim;
  const float* sc = mod + b * ModW + sc_off * Hdim;
  f16* o = o16 + (size_t)row * Hdim;
  for (int i = tid; i < Hdim; i += 256)
    o[i] = __float2half((xr[i] - mu) * rstd * (1.f + sc[i]) + sh[i]);
}

// ------------------- tensor-core GEMM (NT, fp16) ----------------------------
__device__ __forceinline__ float gelu_tanh(float v) {
  const float c = 0.7978845608028654f;
  return 0.5f * v * (1.f + tanhf(c * (v + 0.044715f * v * v * v)));
}

#define EPI_BIAS    0
#define EPI_GELU    1
#define EPI_RESGATE 2

__device__ __forceinline__ void mma_f16(float c[4], const uint32_t a[4],
                                        const uint32_t b[2]) {
  asm volatile(
      "mma.sync.aligned.m16n8k16.row.col.f32.f16.f16.f32 "
      "{%0,%1,%2,%3}, {%4,%5,%6,%7}, {%8,%9}, {%0,%1,%2,%3};"
      : "+f"(c[0]), "+f"(c[1]), "+f"(c[2]), "+f"(c[3])
      : "r"(a[0]), "r"(a[1]), "r"(a[2]), "r"(a[3]), "r"(b[0]), "r"(b[1]));
}
__device__ __forceinline__ void mma_f16_k8(float c[4], const uint32_t a[2],
                                           uint32_t b0) {
  asm volatile(
      "mma.sync.aligned.m16n8k8.row.col.f32.f16.f16.f32 "
      "{%0,%1,%2,%3}, {%4,%5}, {%6}, {%0,%1,%2,%3};"
      : "+f"(c[0]), "+f"(c[1]), "+f"(c[2]), "+f"(c[3])
      : "r"(a[0]), "r"(a[1]), "r"(b0));
}

__device__ __forceinline__ void ldsm4(uint32_t r[4], uint32_t addr) {
  asm volatile("ldmatrix.sync.aligned.m8n8.x4.shared.b16 {%0,%1,%2,%3}, [%4];"
               : "=r"(r[0]), "=r"(r[1]), "=r"(r[2]), "=r"(r[3]) : "r"(addr));
}
__device__ __forceinline__ void ldsm4t(uint32_t r[4], uint32_t addr) {
  asm volatile(
      "ldmatrix.sync.aligned.m8n8.x4.trans.shared.b16 {%0,%1,%2,%3}, [%4];"
      : "=r"(r[0]), "=r"(r[1]), "=r"(r[2]), "=r"(r[3]) : "r"(addr));
}

__device__ __forceinline__ void cp16(uint32_t dst, const void* src, bool p) {
  int sz = p ? 16 : 0;
  asm volatile("cp.async.cg.shared.global [%0], [%1], 16, %2;\n"
               :: "r"(dst), "l"(src), "r"(sz));
}

// K-tile 64: plane = 128 rows x 144B (128B data + 16B pad). 2 stages.
#define PL_B    18432
#define STAGE_B (2 * PL_B)       // A, B = 36864
#define GSMEM   (2 * STAGE_B)    // 73728

template <int EPI, bool OUTF, bool OUTB>
__global__ __launch_bounds__(256, 2) void gemm_tc(
    const f16* __restrict__ A, const f16* __restrict__ W,
    const float* __restrict__ bias, const float* __restrict__ res,
    const float* __restrict__ gate, float* __restrict__ C,
    f16* __restrict__ C16,
    int M, int N, int K) {
  extern __shared__ char smc[];
  uint32_t sbase = (uint32_t)__cvta_generic_to_shared(smc);
  int tid = threadIdx.x;
  int warp = tid >> 5, lane = tid & 31;
  int wm = warp & 3, wn = warp >> 2;     // 4 warps M x 2 warps N
  int m0 = blockIdx.y << 7, n0 = blockIdx.x << 7;

  float acc[2][8][4];
#pragma unroll
  for (int mt = 0; mt < 2; mt++)
#pragma unroll
    for (int nt = 0; nt < 8; nt++)
#pragma unroll
      for (int f = 0; f < 4; f++) acc[mt][nt][f] = 0.f;

  int lq = lane & 7, lb = (lane >> 3) & 1, lh = lane >> 4;
  uint32_t offA[2], offB[4];
#pragma unroll
  for (int mt = 0; mt < 2; mt++)
    offA[mt] = (uint32_t)((wm * 32 + mt * 16 + lq + lb * 8) * 144 + lh * 16);
#pragma unroll
  for (int j = 0; j < 4; j++)
    offB[j] = (uint32_t)(PL_B +
                         (wn * 64 + j * 16 + lq + lh * 8) * 144 + lb * 16);

  const int nk = K >> 6;

  auto issue = [&](int kt, int s) {
    uint32_t st = sbase + s * STAGE_B;
    int k0 = kt << 6;
#pragma unroll
    for (int i = 0; i < 8; i++) {
      int idx = tid + (i << 8);
      int pl = idx >> 10;          // 0=A, 1=B
      int cc = idx & 1023;
      int row = cc >> 3, ch = cc & 7;
      uint32_t d = st + pl * PL_B + row * 144 + ch * 16;
      const f16* src;
      bool ok = true;
      if (pl == 0) {
        int gm = m0 + row;
        ok = gm < M;
        src = A + (size_t)(ok ? gm : 0) * K + k0 + ch * 8;
      } else {
        src = W + (size_t)(n0 + row) * K + k0 + ch * 8;
      }
      cp16(d, src, ok);
    }
    asm volatile("cp.async.commit_group;\n");
  };

  issue(0, 0);
  for (int kt = 0; kt < nk; kt++) {
    int s = kt & 1;
    if (kt + 1 < nk) {
      issue(kt + 1, s ^ 1);
      asm volatile("cp.async.wait_group 1;\n");
    } else {
      asm volatile("cp.async.wait_group 0;\n");
    }
    __syncthreads();

    uint32_t sb = sbase + s * STAGE_B;
#pragma unroll
    for (int ks = 0; ks < 4; ks++) {
      uint32_t a_[2][4];
#pragma unroll
      for (int mt = 0; mt < 2; mt++)
        ldsm4(a_[mt], sb + offA[mt] + ks * 32);
#pragma unroll
      for (int jp = 0; jp < 2; jp++) {
        uint32_t b0[4], b1[4];
        ldsm4(b0, sb + offB[2 * jp]     + ks * 32);
        ldsm4(b1, sb + offB[2 * jp + 1] + ks * 32);
        float (*a0)[4] = acc[0], (*a1)[4] = acc[1];
        int q = 4 * jp;
        mma_f16(a0[q],     a_[0], b0);
        mma_f16(a0[q + 1], a_[0], b0 + 2);
        mma_f16(a1[q],     a_[1], b0);
        mma_f16(a1[q + 1], a_[1], b0 + 2);
        mma_f16(a0[q + 2], a_[0], b1);
        mma_f16(a0[q + 3], a_[0], b1 + 2);
        mma_f16(a1[q + 2], a_[1], b1);
        mma_f16(a1[q + 3], a_[1], b1 + 2);
      }
    }
    __syncthreads();
  }

  int g = lane >> 2, tg = lane & 3;
#pragma unroll
  for (int mt = 0; mt < 2; mt++) {
#pragma unroll
    for (int half = 0; half < 2; half++) {
      int m = m0 + wm * 32 + mt * 16 + g + half * 8;
      if (m >= M) continue;
      int bq = m >> 10;
#pragma unroll
      for (int nt = 0; nt < 8; nt++) {
        int n = n0 + wn * 64 + nt * 8 + tg * 2;
        float v0 = acc[mt][nt][half * 2 + 0];
        float v1 = acc[mt][nt][half * 2 + 1];
        if (bias) { v0 += bias[n]; v1 += bias[n + 1]; }
        if (EPI == EPI_GELU) { v0 = gelu_tanh(v0); v1 = gelu_tanh(v1); }
        if (EPI == EPI_RESGATE) {
          float g0 = 1.f, g1 = 1.f;
          if (gate) { g0 = gate[bq * ModW + n]; g1 = gate[bq * ModW + n + 1]; }
          v0 = res[(size_t)m * N + n] + g0 * v0;
          v1 = res[(size_t)m * N + n + 1] + g1 * v1;
        }
        if (OUTF)
          *(float2*)(C + (size_t)m * N + n) = make_float2(v0, v1);
        if (OUTB)
          *(f162*)(C16 + (size_t)m * N + n) = __floats2half2_rn(v0, v1);
      }
    }
  }
}

// ---------------- tensor-core flash attention (fp16) ------------------------
// Templated on KV tile width: 128 for self-attn, 80 for cross-attn (kv=77).
#define ARB   176
#define APL   (128 * ARB)
#define ATSM  (5 * APL)            // Q + 2 stages x (K,V)

template <int KVT>
__global__ __launch_bounds__(256) void attn_tc(
    const f16* __restrict__ Q, long long qbs, int ldq,
    const f16* __restrict__ Kp, const f16* __restrict__ Vp,
    long long kbs, int ldk,
    f16* __restrict__ O,
    int kv_len, float sl2e) {
  constexpr int NT16 = KVT / 16;    // n16 tiles per KV tile
  constexpr int NJ   = KVT / 8;     // n8 accumulator tiles
  constexpr int KC   = KVT / 16;    // PV k16 chunks
  extern __shared__ char smb[];
  uint32_t sb = (uint32_t)__cvta_generic_to_shared(smb);
  int b = blockIdx.z, h = blockIdx.y;
  int m0 = blockIdx.x * 128;
  int tid = threadIdx.x, warp = tid >> 5, lane = tid & 31;
  int g = lane >> 2, tg = lane & 3;
  int lq = lane & 7, lb = (lane >> 3) & 1, lh = lane >> 4;

  const f16* Qb = Q  + (size_t)b * qbs + (size_t)m0 * ldq + h * HeadD;
  const f16* Kb = Kp + (size_t)b * kbs + h * HeadD;
  const f16* Vb = Vp + (size_t)b * kbs + h * HeadD;

  // zero hd-padding (cols 72..87) of all 5 planes (V pad cols are read by
  // the np=4 transposed ldsm; K pad never reaches an MMA with the k8 tail)
  for (int i = tid; i < 640; i += 256) {
    int p = i >> 7, r = i & 127;
    uint32_t ad = sb + p * APL + r * ARB + 144;
    asm volatile("st.shared.v4.b32 [%0], {%1,%1,%1,%1};" :: "r"(ad), "r"(0));
    asm volatile("st.shared.v4.b32 [%0], {%1,%1,%1,%1};"
                 :: "r"(ad + 16), "r"(0));
  }

  for (int i = tid; i < 1152; i += 256) {
    int r = i / 9, ch = i % 9;
    cp16(sb + r * ARB + ch * 16, Qb + (size_t)r * ldq + ch * 8, true);
  }

  auto loadKV = [&](int j0, int s) {
    uint32_t st = sb + APL + s * 2 * APL;
    for (int i = tid; i < KVT * 9; i += 256) {
      int r = i / 9, ch = i % 9;
      bool ok = (j0 + r) < kv_len;
      int rc = ok ? (j0 + r) : 0;
      size_t off = (size_t)rc * ldk + ch * 8;
      uint32_t d = st + r * ARB + ch * 16;
      cp16(d,       Kb + off, ok);
      cp16(d + APL, Vb + off, ok);
    }
    asm volatile("cp.async.commit_group;\n");
  };

  int iters = (kv_len + KVT - 1) / KVT;
  loadKV(0, 0);
  if (iters > 1) loadKV(KVT, 1);

  float m0r = -1e30f, m1r = -1e30f, ls0 = 0.f, ls1 = 0.f;
  float oacc[9][4];
#pragma unroll
  for (int nt = 0; nt < 9; nt++)
#pragma unroll
    for (int f = 0; f < 4; f++) oacc[nt][f] = 0.f;

  uint32_t offA = (uint32_t)((warp * 16 + lq + lb * 8) * ARB + lh * 16);
  uint32_t offB = (uint32_t)((lq + lh * 8) * ARB + lb * 16);
  uint32_t offV = (uint32_t)((lq + lb * 8) * ARB + lh * 16);

  for (int it = 0; it < iters; it++) {
    if (it + 1 < iters) {
      if (it > 0) loadKV((it + 1) * KVT, (it + 1) & 1);
      asm volatile("cp.async.wait_group 1;\n");
    } else {
      asm volatile("cp.async.wait_group 0;\n");
    }
    __syncthreads();

    uint32_t kbse = sb + APL + (it & 1) * 2 * APL;

    float sa[NJ][4];
#pragma unroll
    for (int j = 0; j < NJ; j++)
#pragma unroll
      for (int f = 0; f < 4; f++) sa[j][f] = 0.f;

    // ---- S = Q K^T: 4 full k16 steps + 1 k8 tail (HD = 72) ----
#pragma unroll
    for (int ks = 0; ks < 4; ks++) {
      uint32_t a_[4];
      ldsm4(a_, sb + offA + ks * 32);
#pragma unroll
      for (int nt = 0; nt < NT16; nt++) {
        uint32_t bb[4];
        ldsm4(bb, kbse + offB + nt * 16 * ARB + ks * 32);
        mma_f16(sa[2 * nt],     a_, bb);
        mma_f16(sa[2 * nt + 1], a_, bb + 2);
      }
    }
    {
      uint32_t a_[4];
      ldsm4(a_, sb + offA + 4 * 32);       // regs 0,1 = k 64..71
#pragma unroll
      for (int nt = 0; nt < NT16; nt++) {
        uint32_t bb[4];
        ldsm4(bb, kbse + offB + nt * 16 * ARB + 4 * 32);
        mma_f16_k8(sa[2 * nt],     a_, bb[0]);
        mma_f16_k8(sa[2 * nt + 1], a_, bb[2]);
      }
    }

    int j0 = it * KVT;
    bool msk = (j0 + KVT) > kv_len;
    float mx0 = -1e30f, mx1 = -1e30f;
#pragma unroll
    for (int j = 0; j < NJ; j++) {
#pragma unroll
      for (int e = 0; e < 4; e++) {
        float v = sa[j][e] * sl2e;
        if (msk) {
          int col = j * 8 + 2 * tg + (e & 1);
          if (j0 + col >= kv_len) v = -1e30f;
        }
        sa[j][e] = v;
      }
      mx0 = fmaxf(mx0, fmaxf(sa[j][0], sa[j][1]));
      mx1 = fmaxf(mx1, fmaxf(sa[j][2], sa[j][3]));
    }
    mx0 = fmaxf(mx0, __shfl_xor_sync(0xffffffffu, mx0, 1));
    mx0 = fmaxf(mx0, __shfl_xor_sync(0xffffffffu, mx0, 2));
    mx1 = fmaxf(mx1, __shfl_xor_sync(0xffffffffu, mx1, 1));
    mx1 = fmaxf(mx1, __shfl_xor_sync(0xffffffffu, mx1, 2));
    float mn0 = fmaxf(m0r, mx0), mn1 = fmaxf(m1r, mx1);
    float al0 = ex2(m0r - mn0), al1 = ex2(m1r - mn1);
    m0r = mn0; m1r = mn1;

    float s0 = 0.f, s1 = 0.f;
#pragma unroll
    for (int j = 0; j < NJ; j++) {
      float p0 = ex2(sa[j][0] - mn0), p1 = ex2(sa[j][1] - mn0);
      float p2 = ex2(sa[j][2] - mn1), p3 = ex2(sa[j][3] - mn1);
      sa[j][0] = p0; sa[j][1] = p1; sa[j][2] = p2; sa[j][3] = p3;
      s0 += p0 + p1; s1 += p2 + p3;
    }
    s0 += __shfl_xor_sync(0xffffffffu, s0, 1);
    s0 += __shfl_xor_sync(0xffffffffu, s0, 2);
    s1 += __shfl_xor_sync(0xffffffffu, s1, 1);
    s1 += __shfl_xor_sync(0xffffffffu, s1, 2);
    ls0 = ls0 * al0 + s0;
    ls1 = ls1 * al1 + s1;
#pragma unroll
    for (int nt = 0; nt < 9; nt++) {
      oacc[nt][0] *= al0; oacc[nt][1] *= al0;
      oacc[nt][2] *= al1; oacc[nt][3] *= al1;
    }

    uint32_t vbse = kbse + APL;
#pragma unroll
    for (int kc = 0; kc < KC; kc++) {
      uint32_t pa[4];
      pa[0] = pack_f16x2(sa[2 * kc][0],     sa[2 * kc][1]);
      pa[1] = pack_f16x2(sa[2 * kc][2],     sa[2 * kc][3]);
      pa[2] = pack_f16x2(sa[2 * kc + 1][0], sa[2 * kc + 1][1]);
      pa[3] = pack_f16x2(sa[2 * kc + 1][2], sa[2 * kc + 1][3]);
#pragma unroll
      for (int npp = 0; npp < 2; npp++) {
        int np0 = 2 * npp, np1 = 2 * npp + 1;
        uint32_t v0[4], v1[4];
        ldsm4t(v0, vbse + offV + kc * 16 * ARB + np0 * 32);
        ldsm4t(v1, vbse + offV + kc * 16 * ARB + np1 * 32);
        mma_f16(oacc[2 * np0],     pa, v0);
        mma_f16(oacc[2 * np0 + 1], pa, v0 + 2);
        mma_f16(oacc[2 * np1],     pa, v1);
        mma_f16(oacc[2 * np1 + 1], pa, v1 + 2);
      }
      {
        uint32_t v4[4];
        ldsm4t(v4, vbse + offV + kc * 16 * ARB + 4 * 32);
        mma_f16(oacc[8], pa, v4);
      }
    }
    __syncthreads();
  }

  float inv0 = 1.f / ls0, inv1 = 1.f / ls1;
  int r0 = m0 + warp * 16 + g, r1 = r0 + 8;
  size_t base0 = ((size_t)b * Ntok + r0) * Hdim + h * HeadD;
  size_t base1 = ((size_t)b * Ntok + r1) * Hdim + h * HeadD;
#pragma unroll
  for (int nt = 0; nt < 9; nt++) {
    int col = nt * 8 + 2 * tg;
    *(f162*)(O + base0 + col) =
        __floats2half2_rn(oacc[nt][0] * inv0, oacc[nt][1] * inv0);
    *(f162*)(O + base1 + col) =
        __floats2half2_rn(oacc[nt][2] * inv1, oacc[nt][3] * inv1);
  }
}

// ------------------------------ launcher -----------------------------------
static float* sym_f(const void* s) { void* p; cudaGetSymbolAddress(&p, s); return (float*)p; }
static f16*   sym_h(const void* s) { void* p; cudaGetSymbolAddress(&p, s); return (f16*)p; }

extern "C" void kernel_launch(void* const* d_in, const int* in_sizes, int n_in,
                              void* d_out, int out_size) {
  (void)in_sizes; (void)n_in; (void)out_size;
  const float* x        = (const float*)d_in[0];
  const float* c        = (const float*)d_in[1];
  const float* t_emb    = (const float*)d_in[2];
  const float* qkv_w    = (const float*)d_in[3];
  const float* qkv_b    = (const float*)d_in[4];
  const float* proj_w   = (const float*)d_in[5];
  const float* proj_b   = (const float*)d_in[6];
  const float* to_q_w   = (const float*)d_in[7];
  const float* to_k_w   = (const float*)d_in[8];
  const float* to_v_w   = (const float*)d_in[9];
  const float* to_out_w = (const float*)d_in[10];
  const float* to_out_b = (const float*)d_in[11];
  const float* mlp_w1   = (const float*)d_in[12];
  const float* mlp_b1   = (const float*)d_in[13];
  const float* mlp_w2   = (const float*)d_in[14];
  const float* mlp_b2   = (const float*)d_in[15];
  const float* ada_w    = (const float*)d_in[16];
  const float* ada_b    = (const float*)d_in[17];
  float* out = (float*)d_out;

  float *mod = sym_f(&g_mod), *xb = sym_f(&g_xb);
  f16 *ln = sym_h(&g_ln), *at = sym_h(&g_at), *xbh = sym_h(&g_xbh);
  f16 *qkv = sym_h(&g_qkv), *kv = sym_h(&g_kv), *hid = sym_h(&g_hid);
  f16 *cc = sym_h(&g_c);
  f16 *wqkv = sym_h(&g_wqkv), *wpr = sym_h(&g_wpr), *wq = sym_h(&g_wq);
  f16 *wkv = sym_h(&g_wkv), *wo = sym_h(&g_wo);
  f16 *w1 = sym_h(&g_w1), *w2 = sym_h(&g_w2);

  cudaFuncSetAttribute(attn_tc<128>,
                       cudaFuncAttributeMaxDynamicSharedMemorySize, ATSM);
  cudaFuncSetAttribute(attn_tc<80>,
                       cudaFuncAttributeMaxDynamicSharedMemorySize, ATSM);
#define SETSM(k) cudaFuncSetAttribute(k, \
    cudaFuncAttributeMaxDynamicSharedMemorySize, GSMEM)
  SETSM((gemm_tc<EPI_BIAS, false, true>));
  SETSM((gemm_tc<EPI_GELU, false, true>));
  SETSM((gemm_tc<EPI_RESGATE, true, true>));
  SETSM((gemm_tc<EPI_RESGATE, true, false>));
#undef SETSM

  const float sl2e = (1.f / sqrtf((float)HeadD)) * 1.4426950408889634f;

  // conversions: 8 weight tensors + context, all single fp16
  {
    CvtJobs J;
    const float* s[9] = {qkv_w, proj_w, to_q_w, to_k_w, to_v_w,
                         to_out_w, mlp_w1, mlp_w2, c};
    f16* dd[9] = {wqkv, wpr, wq, wkv, wkv + Hdim * CtxD, wo, w1, w2, cc};
    int nn[9] = {3 * Hdim * Hdim, Hdim * Hdim, Hdim * Hdim, Hdim * CtxD,
                 Hdim * CtxD, Hdim * Hdim, MlpD * Hdim, Hdim * MlpD,
                 Crows * CtxD};
    for (int i = 0; i < 9; i++) { J.src[i] = s[i]; J.dst[i] = dd[i];
                                  J.n[i] = nn[i]; }
    dim3 g((MlpD * Hdim / 4 + 255) / 256, 9);
    cvt_all_kernel<<<g, 256>>>(J);
  }
  ada_kernel<<<ModW / 128, 128>>>(t_emb, ada_w, ada_b, mod);
  ln_mod_kernel<<<Mrows, 256>>>(x, mod, 0, 1, ln);
  // qkv
  {
    dim3 g(3 * Hdim / 128, Mrows / 128);
    gemm_tc<EPI_BIAS, false, true><<<g, 256, GSMEM>>>(
        ln, wqkv, qkv_b, nullptr, nullptr,
        nullptr, qkv, Mrows, 3 * Hdim, Hdim);
  }
  // self-attention (KV tile 128)
  {
    dim3 g(Ntok / 128, NHead, Bsz);
    attn_tc<128><<<g, 256, ATSM>>>(
        qkv, (long long)Ntok * 3 * Hdim, 3 * Hdim,
        qkv + Hdim, qkv + 2 * Hdim, (long long)Ntok * 3 * Hdim, 3 * Hdim,
        at, Ntok, sl2e);
  }
  // proj + gated residual; cross-attn Q
  {
    dim3 g(Hdim / 128, Mrows / 128);
    gemm_tc<EPI_RESGATE, true, true><<<g, 256, GSMEM>>>(
        at, wpr, proj_b, x, mod + 2 * Hdim,
        xb, xbh, Mrows, Hdim, Hdim);
    gemm_tc<EPI_BIAS, false, true><<<g, 256, GSMEM>>>(
        xbh, wq, nullptr, nullptr, nullptr,
        nullptr, ln, Mrows, Hdim, Hdim);
  }
  // cross-attn K|V (merged weights, one GEMM)
  {
    dim3 g(KVW / 128, (Crows + 127) / 128);
    gemm_tc<EPI_BIAS, false, true><<<g, 256, GSMEM>>>(
        cc, wkv, nullptr, nullptr, nullptr,
        nullptr, kv, Crows, KVW, CtxD);
  }
  // cross-attention (KV tile 80 covers kv_len 77 in one iteration)
  {
    dim3 g(Ntok / 128, NHead, Bsz);
    attn_tc<80><<<g, 256, ATSM>>>(
        ln, (long long)Ntok * Hdim, Hdim,
        kv, kv + Hdim, (long long)CtxT * KVW, KVW,
        at, CtxT, sl2e);
  }
  // to_out + residual
  {
    dim3 g(Hdim / 128, Mrows / 128);
    gemm_tc<EPI_RESGATE, true, false><<<g, 256, GSMEM>>>(
        at, wo, to_out_b, xb, nullptr,
        xb, nullptr, Mrows, Hdim, Hdim);
  }
  ln_mod_kernel<<<Mrows, 256>>>(xb, mod, 3, 4, ln);
  // MLP
  {
    dim3 g1(MlpD / 128, Mrows / 128);
    gemm_tc<EPI_GELU, false, true><<<g1, 256, GSMEM>>>(
        ln, w1, mlp_b1, nullptr, nullptr,
        nullptr, hid, Mrows, MlpD, Hdim);
    dim3 g2(Hdim / 128, Mrows / 128);
    gemm_tc<EPI_RESGATE, true, false><<<g2, 256, GSMEM>>>(
        hid, w2, mlp_b2, xb, mod + 5 * Hdim,
        out, nullptr, Mrows, Hdim, MlpD);
  }
}

// round 13
// speedup vs baseline: 1.0264x; 1.0136x over previous
#include <cuda_runtime.h>
#include <cuda_fp16.h>
#include <math.h>
#include <stdint.h>

// ---------------------------------------------------------------------------
// DiT block. Round 13: R12 kernels unchanged (fp16 mma.sync GEMMs, flash
// attention with k8 tail + 80-wide cross-attn KV tile). New: second stream
// forked via events inside graph capture so (cvt -> kv GEMM) overlaps the
// (ada, ln, qkv, self-attn, proj, to_q) chain.
// ---------------------------------------------------------------------------

#define Bsz   8
#define Ntok  1024
#define Hdim  1152
#define NHead 16
#define HeadD 72
#define CtxD  768
#define CtxT  77
#define MlpD  4608
#define Mrows (Bsz * Ntok)     // 8192
#define Crows (Bsz * CtxT)     // 616
#define ModW  (6 * Hdim)       // 6912
#define KVW   (2 * Hdim)       // 2304

typedef __half  f16;
typedef __half2 f162;

// ------------------------- scratch (no allocations) ------------------------
__device__ float g_mod [Bsz * ModW];
__device__ float g_xb  [Mrows * Hdim];

__device__ f16 g_ln  [Mrows * Hdim];
__device__ f16 g_at  [Mrows * Hdim];
__device__ f16 g_xbh [Mrows * Hdim];
__device__ f16 g_qkv [Mrows * 3 * Hdim];
__device__ f16 g_kv  [Crows * KVW];
__device__ f16 g_hid [Mrows * MlpD];
__device__ f16 g_c   [Crows * CtxD];
__device__ f16 g_wqkv[3 * Hdim * Hdim];
__device__ f16 g_wpr [Hdim * Hdim];
__device__ f16 g_wq  [Hdim * Hdim];
__device__ f16 g_wkv [KVW * CtxD];
__device__ f16 g_wo  [Hdim * Hdim];
__device__ f16 g_w1  [MlpD * Hdim];
__device__ f16 g_w2  [Hdim * MlpD];

// ------------------------------ helpers ------------------------------------
__device__ __forceinline__ float ex2(float x) {
  float y; asm("ex2.approx.f32 %0, %1;" : "=f"(y) : "f"(x)); return y;
}
__device__ __forceinline__ uint32_t pack_f16x2(float lo, float hi) {
  uint32_t d;
  asm("cvt.rn.f16x2.f32 %0, %1, %2;" : "=r"(d) : "f"(hi), "f"(lo));
  return d;
}

// -------------------- fused weight/context conversion ----------------------
struct CvtJobs {
  const float* src[9];
  f16* dst[9];
  int n[9];
};

__global__ __launch_bounds__(256) void cvt_all_kernel(CvtJobs J) {
  int t = blockIdx.y;
  int i = (blockIdx.x * 256 + threadIdx.x) * 4;
  if (i >= J.n[t]) return;
  float4 v = *(const float4*)(J.src[t] + i);
  f16* d = J.dst[t];
  *(f162*)(d + i)     = __floats2half2_rn(v.x, v.y);
  *(f162*)(d + i + 2) = __floats2half2_rn(v.z, v.w);
}

// --------------------------- adaLN modulation ------------------------------
__global__ __launch_bounds__(128) void ada_kernel(
    const float* __restrict__ t_emb, const float* __restrict__ ada_w,
    const float* __restrict__ ada_b, float* __restrict__ mod) {
  __shared__ float se[Bsz * Hdim];
  int tid = threadIdx.x;
  for (int i = tid; i < Bsz * Hdim; i += 128) {
    float v = t_emb[i];
    se[i] = v / (1.f + __expf(-v));
  }
  __syncthreads();
  int j = blockIdx.x * 128 + tid;
  const float* w = ada_w + (size_t)j * Hdim;
  float acc[Bsz];
#pragma unroll
  for (int b = 0; b < Bsz; b++) acc[b] = 0.f;
  for (int k = 0; k < Hdim; k += 4) {
    float4 wv = *(const float4*)(w + k);
#pragma unroll
    for (int b = 0; b < Bsz; b++) {
      const float* s = se + b * Hdim + k;
      acc[b] += wv.x * s[0] + wv.y * s[1] + wv.z * s[2] + wv.w * s[3];
    }
  }
  float bb = ada_b[j];
#pragma unroll
  for (int b = 0; b < Bsz; b++) mod[b * ModW + j] = acc[b] + bb;
}

// ----------------- LayerNorm + modulate -> fp16 -----------------------------
__global__ __launch_bounds__(256) void ln_mod_kernel(
    const float* __restrict__ x, const float* __restrict__ mod,
    int sh_off, int sc_off, f16* __restrict__ o16) {
  int row = blockIdx.x;
  int b = row >> 10;
  const float* xr = x + (size_t)row * Hdim;
  int tid = threadIdx.x;
  float s = 0.f, ss = 0.f;
  for (int i = tid; i < Hdim; i += 256) {
    float v = xr[i];
    s += v; ss += v * v;
  }
#pragma unroll
  for (int o = 16; o > 0; o >>= 1) {
    s  += __shfl_xor_sync(0xffffffffu, s, o);
    ss += __shfl_xor_sync(0xffffffffu, ss, o);
  }
  __shared__ float rs[8], rss[8], stat[2];
  int w = tid >> 5;
  if ((tid & 31) == 0) { rs[w] = s; rss[w] = ss; }
  __syncthreads();
  if (tid == 0) {
    float S = 0.f, SS = 0.f;
#pragma unroll
    for (int i = 0; i < 8; i++) { S += rs[i]; SS += rss[i]; }
    float mu = S * (1.f / Hdim);
    float var = SS * (1.f / Hdim) - mu * mu;
    stat[0] = mu;
    stat[1] = rsqrtf(var + 1e-6f);
  }
  __syncthreads();
  float mu = stat[0], rstd = stat[1];
  const float* sh = mod + b * ModW + sh_off * Hdim;
  const float* sc = mod + b * ModW + sc_off * Hdim;
  f16* o = o16 + (size_t)row * Hdim;
  for (int i = tid; i < Hdim; i += 256)
    o[i] = __float2half((xr[i] - mu) * rstd * (1.f + sc[i]) + sh[i]);
}

// ------------------- tensor-core GEMM (NT, fp16) ----------------------------
__device__ __forceinline__ float gelu_tanh(float v) {
  const float c = 0.7978845608028654f;
  return 0.5f * v * (1.f + tanhf(c * (v + 0.044715f * v * v * v)));
}

#define EPI_BIAS    0
#define EPI_GELU    1
#define EPI_RESGATE 2

__device__ __forceinline__ void mma_f16(float c[4], const uint32_t a[4],
                                        const uint32_t b[2]) {
  asm volatile(
      "mma.sync.aligned.m16n8k16.row.col.f32.f16.f16.f32 "
      "{%0,%1,%2,%3}, {%4,%5,%6,%7}, {%8,%9}, {%0,%1,%2,%3};"
      : "+f"(c[0]), "+f"(c[1]), "+f"(c[2]), "+f"(c[3])
      : "r"(a[0]), "r"(a[1]), "r"(a[2]), "r"(a[3]), "r"(b[0]), "r"(b[1]));
}
__device__ __forceinline__ void mma_f16_k8(float c[4], const uint32_t a[2],
                                           uint32_t b0) {
  asm volatile(
      "mma.sync.aligned.m16n8k8.row.col.f32.f16.f16.f32 "
      "{%0,%1,%2,%3}, {%4,%5}, {%6}, {%0,%1,%2,%3};"
      : "+f"(c[0]), "+f"(c[1]), "+f"(c[2]), "+f"(c[3])
      : "r"(a[0]), "r"(a[1]), "r"(b0));
}

__device__ __forceinline__ void ldsm4(uint32_t r[4], uint32_t addr) {
  asm volatile("ldmatrix.sync.aligned.m8n8.x4.shared.b16 {%0,%1,%2,%3}, [%4];"
               : "=r"(r[0]), "=r"(r[1]), "=r"(r[2]), "=r"(r[3]) : "r"(addr));
}
__device__ __forceinline__ void ldsm4t(uint32_t r[4], uint32_t addr) {
  asm volatile(
      "ldmatrix.sync.aligned.m8n8.x4.trans.shared.b16 {%0,%1,%2,%3}, [%4];"
      : "=r"(r[0]), "=r"(r[1]), "=r"(r[2]), "=r"(r[3]) : "r"(addr));
}

__device__ __forceinline__ void cp16(uint32_t dst, const void* src, bool p) {
  int sz = p ? 16 : 0;
  asm volatile("cp.async.cg.shared.global [%0], [%1], 16, %2;\n"
               :: "r"(dst), "l"(src), "r"(sz));
}

// K-tile 64: plane = 128 rows x 144B (128B data + 16B pad). 2 stages.
#define PL_B    18432
#define STAGE_B (2 * PL_B)       // A, B = 36864
#define GSMEM   (2 * STAGE_B)    // 73728

template <int EPI, bool OUTF, bool OUTB>
__global__ __launch_bounds__(256, 2) void gemm_tc(
    const f16* __restrict__ A, const f16* __restrict__ W,
    const float* __restrict__ bias, const float* __restrict__ res,
    const float* __restrict__ gate, float* __restrict__ C,
    f16* __restrict__ C16,
    int M, int N, int K) {
  extern __shared__ char smc[];
  uint32_t sbase = (uint32_t)__cvta_generic_to_shared(smc);
  int tid = threadIdx.x;
  int warp = tid >> 5, lane = tid & 31;
  int wm = warp & 3, wn = warp >> 2;     // 4 warps M x 2 warps N
  int m0 = blockIdx.y << 7, n0 = blockIdx.x << 7;

  float acc[2][8][4];
#pragma unroll
  for (int mt = 0; mt < 2; mt++)
#pragma unroll
    for (int nt = 0; nt < 8; nt++)
#pragma unroll
      for (int f = 0; f < 4; f++) acc[mt][nt][f] = 0.f;

  int lq = lane & 7, lb = (lane >> 3) & 1, lh = lane >> 4;
  uint32_t offA[2], offB[4];
#pragma unroll
  for (int mt = 0; mt < 2; mt++)
    offA[mt] = (uint32_t)((wm * 32 + mt * 16 + lq + lb * 8) * 144 + lh * 16);
#pragma unroll
  for (int j = 0; j < 4; j++)
    offB[j] = (uint32_t)(PL_B +
                         (wn * 64 + j * 16 + lq + lh * 8) * 144 + lb * 16);

  const int nk = K >> 6;

  auto issue = [&](int kt, int s) {
    uint32_t st = sbase + s * STAGE_B;
    int k0 = kt << 6;
#pragma unroll
    for (int i = 0; i < 8; i++) {
      int idx = tid + (i << 8);
      int pl = idx >> 10;          // 0=A, 1=B
      int cc = idx & 1023;
      int row = cc >> 3, ch = cc & 7;
      uint32_t d = st + pl * PL_B + row * 144 + ch * 16;
      const f16* src;
      bool ok = true;
      if (pl == 0) {
        int gm = m0 + row;
        ok = gm < M;
        src = A + (size_t)(ok ? gm : 0) * K + k0 + ch * 8;
      } else {
        src = W + (size_t)(n0 + row) * K + k0 + ch * 8;
      }
      cp16(d, src, ok);
    }
    asm volatile("cp.async.commit_group;\n");
  };

  issue(0, 0);
  for (int kt = 0; kt < nk; kt++) {
    int s = kt & 1;
    if (kt + 1 < nk) {
      issue(kt + 1, s ^ 1);
      asm volatile("cp.async.wait_group 1;\n");
    } else {
      asm volatile("cp.async.wait_group 0;\n");
    }
    __syncthreads();

    uint32_t sb = sbase + s * STAGE_B;
#pragma unroll
    for (int ks = 0; ks < 4; ks++) {
      uint32_t a_[2][4];
#pragma unroll
      for (int mt = 0; mt < 2; mt++)
        ldsm4(a_[mt], sb + offA[mt] + ks * 32);
#pragma unroll
      for (int jp = 0; jp < 2; jp++) {
        uint32_t b0[4], b1[4];
        ldsm4(b0, sb + offB[2 * jp]     + ks * 32);
        ldsm4(b1, sb + offB[2 * jp + 1] + ks * 32);
        float (*a0)[4] = acc[0], (*a1)[4] = acc[1];
        int q = 4 * jp;
        mma_f16(a0[q],     a_[0], b0);
        mma_f16(a0[q + 1], a_[0], b0 + 2);
        mma_f16(a1[q],     a_[1], b0);
        mma_f16(a1[q + 1], a_[1], b0 + 2);
        mma_f16(a0[q + 2], a_[0], b1);
        mma_f16(a0[q + 3], a_[0], b1 + 2);
        mma_f16(a1[q + 2], a_[1], b1);
        mma_f16(a1[q + 3], a_[1], b1 + 2);
      }
    }
    __syncthreads();
  }

  int g = lane >> 2, tg = lane & 3;
#pragma unroll
  for (int mt = 0; mt < 2; mt++) {
#pragma unroll
    for (int half = 0; half < 2; half++) {
      int m = m0 + wm * 32 + mt * 16 + g + half * 8;
      if (m >= M) continue;
      int bq = m >> 10;
#pragma unroll
      for (int nt = 0; nt < 8; nt++) {
        int n = n0 + wn * 64 + nt * 8 + tg * 2;
        float v0 = acc[mt][nt][half * 2 + 0];
        float v1 = acc[mt][nt][half * 2 + 1];
        if (bias) { v0 += bias[n]; v1 += bias[n + 1]; }
        if (EPI == EPI_GELU) { v0 = gelu_tanh(v0); v1 = gelu_tanh(v1); }
        if (EPI == EPI_RESGATE) {
          float g0 = 1.f, g1 = 1.f;
          if (gate) { g0 = gate[bq * ModW + n]; g1 = gate[bq * ModW + n + 1]; }
          v0 = res[(size_t)m * N + n] + g0 * v0;
          v1 = res[(size_t)m * N + n + 1] + g1 * v1;
        }
        if (OUTF)
          *(float2*)(C + (size_t)m * N + n) = make_float2(v0, v1);
        if (OUTB)
          *(f162*)(C16 + (size_t)m * N + n) = __floats2half2_rn(v0, v1);
      }
    }
  }
}

// ---------------- tensor-core flash attention (fp16) ------------------------
// Templated on KV tile width: 128 for self-attn, 80 for cross-attn (kv=77).
#define ARB   176
#define APL   (128 * ARB)
#define ATSM  (5 * APL)            // Q + 2 stages x (K,V)

template <int KVT>
__global__ __launch_bounds__(256) void attn_tc(
    const f16* __restrict__ Q, long long qbs, int ldq,
    const f16* __restrict__ Kp, const f16* __restrict__ Vp,
    long long kbs, int ldk,
    f16* __restrict__ O,
    int kv_len, float sl2e) {
  constexpr int NT16 = KVT / 16;
  constexpr int NJ   = KVT / 8;
  constexpr int KC   = KVT / 16;
  extern __shared__ char smb[];
  uint32_t sb = (uint32_t)__cvta_generic_to_shared(smb);
  int b = blockIdx.z, h = blockIdx.y;
  int m0 = blockIdx.x * 128;
  int tid = threadIdx.x, warp = tid >> 5, lane = tid & 31;
  int g = lane >> 2, tg = lane & 3;
  int lq = lane & 7, lb = (lane >> 3) & 1, lh = lane >> 4;

  const f16* Qb = Q  + (size_t)b * qbs + (size_t)m0 * ldq + h * HeadD;
  const f16* Kb = Kp + (size_t)b * kbs + h * HeadD;
  const f16* Vb = Vp + (size_t)b * kbs + h * HeadD;

  for (int i = tid; i < 640; i += 256) {
    int p = i >> 7, r = i & 127;
    uint32_t ad = sb + p * APL + r * ARB + 144;
    asm volatile("st.shared.v4.b32 [%0], {%1,%1,%1,%1};" :: "r"(ad), "r"(0));
    asm volatile("st.shared.v4.b32 [%0], {%1,%1,%1,%1};"
                 :: "r"(ad + 16), "r"(0));
  }

  for (int i = tid; i < 1152; i += 256) {
    int r = i / 9, ch = i % 9;
    cp16(sb + r * ARB + ch * 16, Qb + (size_t)r * ldq + ch * 8, true);
  }

  auto loadKV = [&](int j0, int s) {
    uint32_t st = sb + APL + s * 2 * APL;
    for (int i = tid; i < KVT * 9; i += 256) {
      int r = i / 9, ch = i % 9;
      bool ok = (j0 + r) < kv_len;
      int rc = ok ? (j0 + r) : 0;
      size_t off = (size_t)rc * ldk + ch * 8;
      uint32_t d = st + r * ARB + ch * 16;
      cp16(d,       Kb + off, ok);
      cp16(d + APL, Vb + off, ok);
    }
    asm volatile("cp.async.commit_group;\n");
  };

  int iters = (kv_len + KVT - 1) / KVT;
  loadKV(0, 0);
  if (iters > 1) loadKV(KVT, 1);

  float m0r = -1e30f, m1r = -1e30f, ls0 = 0.f, ls1 = 0.f;
  float oacc[9][4];
#pragma unroll
  for (int nt = 0; nt < 9; nt++)
#pragma unroll
    for (int f = 0; f < 4; f++) oacc[nt][f] = 0.f;

  uint32_t offA = (uint32_t)((warp * 16 + lq + lb * 8) * ARB + lh * 16);
  uint32_t offB = (uint32_t)((lq + lh * 8) * ARB + lb * 16);
  uint32_t offV = (uint32_t)((lq + lb * 8) * ARB + lh * 16);

  for (int it = 0; it < iters; it++) {
    if (it + 1 < iters) {
      if (it > 0) loadKV((it + 1) * KVT, (it + 1) & 1);
      asm volatile("cp.async.wait_group 1;\n");
    } else {
      asm volatile("cp.async.wait_group 0;\n");
    }
    __syncthreads();

    uint32_t kbse = sb + APL + (it & 1) * 2 * APL;

    float sa[NJ][4];
#pragma unroll
    for (int j = 0; j < NJ; j++)
#pragma unroll
      for (int f = 0; f < 4; f++) sa[j][f] = 0.f;

#pragma unroll
    for (int ks = 0; ks < 4; ks++) {
      uint32_t a_[4];
      ldsm4(a_, sb + offA + ks * 32);
#pragma unroll
      for (int nt = 0; nt < NT16; nt++) {
        uint32_t bb[4];
        ldsm4(bb, kbse + offB + nt * 16 * ARB + ks * 32);
        mma_f16(sa[2 * nt],     a_, bb);
        mma_f16(sa[2 * nt + 1], a_, bb + 2);
      }
    }
    {
      uint32_t a_[4];
      ldsm4(a_, sb + offA + 4 * 32);
#pragma unroll
      for (int nt = 0; nt < NT16; nt++) {
        uint32_t bb[4];
        ldsm4(bb, kbse + offB + nt * 16 * ARB + 4 * 32);
        mma_f16_k8(sa[2 * nt],     a_, bb[0]);
        mma_f16_k8(sa[2 * nt + 1], a_, bb[2]);
      }
    }

    int j0 = it * KVT;
    bool msk = (j0 + KVT) > kv_len;
    float mx0 = -1e30f, mx1 = -1e30f;
#pragma unroll
    for (int j = 0; j < NJ; j++) {
#pragma unroll
      for (int e = 0; e < 4; e++) {
        float v = sa[j][e] * sl2e;
        if (msk) {
          int col = j * 8 + 2 * tg + (e & 1);
          if (j0 + col >= kv_len) v = -1e30f;
        }
        sa[j][e] = v;
      }
      mx0 = fmaxf(mx0, fmaxf(sa[j][0], sa[j][1]));
      mx1 = fmaxf(mx1, fmaxf(sa[j][2], sa[j][3]));
    }
    mx0 = fmaxf(mx0, __shfl_xor_sync(0xffffffffu, mx0, 1));
    mx0 = fmaxf(mx0, __shfl_xor_sync(0xffffffffu, mx0, 2));
    mx1 = fmaxf(mx1, __shfl_xor_sync(0xffffffffu, mx1, 1));
    mx1 = fmaxf(mx1, __shfl_xor_sync(0xffffffffu, mx1, 2));
    float mn0 = fmaxf(m0r, mx0), mn1 = fmaxf(m1r, mx1);
    float al0 = ex2(m0r - mn0), al1 = ex2(m1r - mn1);
    m0r = mn0; m1r = mn1;

    float s0 = 0.f, s1 = 0.f;
#pragma unroll
    for (int j = 0; j < NJ; j++) {
      float p0 = ex2(sa[j][0] - mn0), p1 = ex2(sa[j][1] - mn0);
      float p2 = ex2(sa[j][2] - mn1), p3 = ex2(sa[j][3] - mn1);
      sa[j][0] = p0; sa[j][1] = p1; sa[j][2] = p2; sa[j][3] = p3;
      s0 += p0 + p1; s1 += p2 + p3;
    }
    s0 += __shfl_xor_sync(0xffffffffu, s0, 1);
    s0 += __shfl_xor_sync(0xffffffffu, s0, 2);
    s1 += __shfl_xor_sync(0xffffffffu, s1, 1);
    s1 += __shfl_xor_sync(0xffffffffu, s1, 2);
    ls0 = ls0 * al0 + s0;
    ls1 = ls1 * al1 + s1;
#pragma unroll
    for (int nt = 0; nt < 9; nt++) {
      oacc[nt][0] *= al0; oacc[nt][1] *= al0;
      oacc[nt][2] *= al1; oacc[nt][3] *= al1;
    }

    uint32_t vbse = kbse + APL;
#pragma unroll
    for (int kc = 0; kc < KC; kc++) {
      uint32_t pa[4];
      pa[0] = pack_f16x2(sa[2 * kc][0],     sa[2 * kc][1]);
      pa[1] = pack_f16x2(sa[2 * kc][2],     sa[2 * kc][3]);
      pa[2] = pack_f16x2(sa[2 * kc + 1][0], sa[2 * kc + 1][1]);
      pa[3] = pack_f16x2(sa[2 * kc + 1][2], sa[2 * kc + 1][3]);
#pragma unroll
      for (int npp = 0; npp < 2; npp++) {
        int np0 = 2 * npp, np1 = 2 * npp + 1;
        uint32_t v0[4], v1[4];
        ldsm4t(v0, vbse + offV + kc * 16 * ARB + np0 * 32);
        ldsm4t(v1, vbse + offV + kc * 16 * ARB + np1 * 32);
        mma_f16(oacc[2 * np0],     pa, v0);
        mma_f16(oacc[2 * np0 + 1], pa, v0 + 2);
        mma_f16(oacc[2 * np1],     pa, v1);
        mma_f16(oacc[2 * np1 + 1], pa, v1 + 2);
      }
      {
        uint32_t v4[4];
        ldsm4t(v4, vbse + offV + kc * 16 * ARB + 4 * 32);
        mma_f16(oacc[8], pa, v4);
      }
    }
    __syncthreads();
  }

  float inv0 = 1.f / ls0, inv1 = 1.f / ls1;
  int r0 = m0 + warp * 16 + g, r1 = r0 + 8;
  size_t base0 = ((size_t)b * Ntok + r0) * Hdim + h * HeadD;
  size_t base1 = ((size_t)b * Ntok + r1) * Hdim + h * HeadD;
#pragma unroll
  for (int nt = 0; nt < 9; nt++) {
    int col = nt * 8 + 2 * tg;
    *(f162*)(O + base0 + col) =
        __floats2half2_rn(oacc[nt][0] * inv0, oacc[nt][1] * inv0);
    *(f162*)(O + base1 + col) =
        __floats2half2_rn(oacc[nt][2] * inv1, oacc[nt][3] * inv1);
  }
}

// ------------------------------ launcher -----------------------------------
static float* sym_f(const void* s) { void* p; cudaGetSymbolAddress(&p, s); return (float*)p; }
static f16*   sym_h(const void* s) { void* p; cudaGetSymbolAddress(&p, s); return (f16*)p; }

extern "C" void kernel_launch(void* const* d_in, const int* in_sizes, int n_in,
                              void* d_out, int out_size) {
  (void)in_sizes; (void)n_in; (void)out_size;
  const float* x        = (const float*)d_in[0];
  const float* c        = (const float*)d_in[1];
  const float* t_emb    = (const float*)d_in[2];
  const float* qkv_w    = (const float*)d_in[3];
  const float* qkv_b    = (const float*)d_in[4];
  const float* proj_w   = (const float*)d_in[5];
  const float* proj_b   = (const float*)d_in[6];
  const float* to_q_w   = (const float*)d_in[7];
  const float* to_k_w   = (const float*)d_in[8];
  const float* to_v_w   = (const float*)d_in[9];
  const float* to_out_w = (const float*)d_in[10];
  const float* to_out_b = (const float*)d_in[11];
  const float* mlp_w1   = (const float*)d_in[12];
  const float* mlp_b1   = (const float*)d_in[13];
  const float* mlp_w2   = (const float*)d_in[14];
  const float* mlp_b2   = (const float*)d_in[15];
  const float* ada_w    = (const float*)d_in[16];
  const float* ada_b    = (const float*)d_in[17];
  float* out = (float*)d_out;

  float *mod = sym_f(&g_mod), *xb = sym_f(&g_xb);
  f16 *ln = sym_h(&g_ln), *at = sym_h(&g_at), *xbh = sym_h(&g_xbh);
  f16 *qkv = sym_h(&g_qkv), *kv = sym_h(&g_kv), *hid = sym_h(&g_hid);
  f16 *cc = sym_h(&g_c);
  f16 *wqkv = sym_h(&g_wqkv), *wpr = sym_h(&g_wpr), *wq = sym_h(&g_wq);
  f16 *wkv = sym_h(&g_wkv), *wo = sym_h(&g_wo);
  f16 *w1 = sym_h(&g_w1), *w2 = sym_h(&g_w2);

  cudaFuncSetAttribute(attn_tc<128>,
                       cudaFuncAttributeMaxDynamicSharedMemorySize, ATSM);
  cudaFuncSetAttribute(attn_tc<80>,
                       cudaFuncAttributeMaxDynamicSharedMemorySize, ATSM);
#define SETSM(k) cudaFuncSetAttribute(k, \
    cudaFuncAttributeMaxDynamicSharedMemorySize, GSMEM)
  SETSM((gemm_tc<EPI_BIAS, false, true>));
  SETSM((gemm_tc<EPI_GELU, false, true>));
  SETSM((gemm_tc<EPI_RESGATE, true, true>));
  SETSM((gemm_tc<EPI_RESGATE, true, false>));
#undef SETSM

  const float sl2e = (1.f / sqrtf((float)HeadD)) * 1.4426950408889634f;

  // side stream + fork/join events (host objects only; no device memory).
  cudaStream_t s2;
  cudaStreamCreateWithFlags(&s2, cudaStreamNonBlocking);
  cudaEvent_t evRoot, evCvt, evJoin;
  cudaEventCreateWithFlags(&evRoot, cudaEventDisableTiming);
  cudaEventCreateWithFlags(&evCvt,  cudaEventDisableTiming);
  cudaEventCreateWithFlags(&evJoin, cudaEventDisableTiming);

  // fork s2 off the main (capturing) stream
  cudaEventRecord(evRoot, 0);
  cudaStreamWaitEvent(s2, evRoot, 0);

  // s2 branch: conversions -> cross-attn K|V GEMM
  {
    CvtJobs J;
    const float* s[9] = {qkv_w, proj_w, to_q_w, to_k_w, to_v_w,
                         to_out_w, mlp_w1, mlp_w2, c};
    f16* dd[9] = {wqkv, wpr, wq, wkv, wkv + Hdim * CtxD, wo, w1, w2, cc};
    int nn[9] = {3 * Hdim * Hdim, Hdim * Hdim, Hdim * Hdim, Hdim * CtxD,
                 Hdim * CtxD, Hdim * Hdim, MlpD * Hdim, Hdim * MlpD,
                 Crows * CtxD};
    for (int i = 0; i < 9; i++) { J.src[i] = s[i]; J.dst[i] = dd[i];
                                  J.n[i] = nn[i]; }
    dim3 g((MlpD * Hdim / 4 + 255) / 256, 9);
    cvt_all_kernel<<<g, 256, 0, s2>>>(J);
    cudaEventRecord(evCvt, s2);           // weights ready
    dim3 gkv(KVW / 128, (Crows + 127) / 128);
    gemm_tc<EPI_BIAS, false, true><<<gkv, 256, GSMEM, s2>>>(
        cc, wkv, nullptr, nullptr, nullptr,
        nullptr, kv, Crows, KVW, CtxD);
    cudaEventRecord(evJoin, s2);          // kv ready
  }

  // main branch: ada + ln overlap cvt
  ada_kernel<<<ModW / 128, 128>>>(t_emb, ada_w, ada_b, mod);
  ln_mod_kernel<<<Mrows, 256>>>(x, mod, 0, 1, ln);
  cudaStreamWaitEvent(0, evCvt, 0);       // need wqkv before qkv
  // qkv
  {
    dim3 g(3 * Hdim / 128, Mrows / 128);
    gemm_tc<EPI_BIAS, false, true><<<g, 256, GSMEM>>>(
        ln, wqkv, qkv_b, nullptr, nullptr,
        nullptr, qkv, Mrows, 3 * Hdim, Hdim);
  }
  // self-attention (KV tile 128)
  {
    dim3 g(Ntok / 128, NHead, Bsz);
    attn_tc<128><<<g, 256, ATSM>>>(
        qkv, (long long)Ntok * 3 * Hdim, 3 * Hdim,
        qkv + Hdim, qkv + 2 * Hdim, (long long)Ntok * 3 * Hdim, 3 * Hdim,
        at, Ntok, sl2e);
  }
  // proj + gated residual; cross-attn Q
  {
    dim3 g(Hdim / 128, Mrows / 128);
    gemm_tc<EPI_RESGATE, true, true><<<g, 256, GSMEM>>>(
        at, wpr, proj_b, x, mod + 2 * Hdim,
        xb, xbh, Mrows, Hdim, Hdim);
    gemm_tc<EPI_BIAS, false, true><<<g, 256, GSMEM>>>(
        xbh, wq, nullptr, nullptr, nullptr,
        nullptr, ln, Mrows, Hdim, Hdim);
  }
  // join: kv must be ready before cross-attention
  cudaStreamWaitEvent(0, evJoin, 0);
  // cross-attention (KV tile 80 covers kv_len 77 in one iteration)
  {
    dim3 g(Ntok / 128, NHead, Bsz);
    attn_tc<80><<<g, 256, ATSM>>>(
        ln, (long long)Ntok * Hdim, Hdim,
        kv, kv + Hdim, (long long)CtxT * KVW, KVW,
        at, CtxT, sl2e);
  }
  // to_out + residual
  {
    dim3 g(Hdim / 128, Mrows / 128);
    gemm_tc<EPI_RESGATE, true, false><<<g, 256, GSMEM>>>(
        at, wo, to_out_b, xb, nullptr,
        xb, nullptr, Mrows, Hdim, Hdim);
  }
  ln_mod_kernel<<<Mrows, 256>>>(xb, mod, 3, 4, ln);
  // MLP
  {
    dim3 g1(MlpD / 128, Mrows / 128);
    gemm_tc<EPI_GELU, false, true><<<g1, 256, GSMEM>>>(
        ln, w1, mlp_b1, nullptr, nullptr,
        nullptr, hid, Mrows, MlpD, Hdim);
    dim3 g2(Hdim / 128, Mrows / 128);
    gemm_tc<EPI_RESGATE, true, false><<<g2, 256, GSMEM>>>(
        hid, w2, mlp_b2, xb, mod + 5 * Hdim,
        out, nullptr, Mrows, Hdim, MlpD);
  }
  // note: stream/events intentionally not destroyed here — destroying
  // objects referenced by an in-progress capture is unsafe; kernel_launch
  // is invoked only a handful of times (correctness + capture), so the
  // few leaked host-side handles are harmless and allocation-guard-clean.
}

// round 14
// speedup vs baseline: 1.0350x; 1.0084x over previous
#include <cuda_runtime.h>
#include <cuda_fp16.h>
#include <math.h>
#include <stdint.h>

// ---------------------------------------------------------------------------
// DiT block. Round 14: R13 (fp16 mma.sync GEMMs, flash attention with k8
// tail + 80-wide cross-attn KV, cvt/kv on a forked stream) + ln_mod
// rewritten: row cached in registers via float4, single global read of x,
// vectorized shift/scale loads, 8-byte packed fp16 stores.
// ---------------------------------------------------------------------------

#define Bsz   8
#define Ntok  1024
#define Hdim  1152
#define NHead 16
#define HeadD 72
#define CtxD  768
#define CtxT  77
#define MlpD  4608
#define Mrows (Bsz * Ntok)     // 8192
#define Crows (Bsz * CtxT)     // 616
#define ModW  (6 * Hdim)       // 6912
#define KVW   (2 * Hdim)       // 2304

typedef __half  f16;
typedef __half2 f162;

// ------------------------- scratch (no allocations) ------------------------
__device__ float g_mod [Bsz * ModW];
__device__ float g_xb  [Mrows * Hdim];

__device__ f16 g_ln  [Mrows * Hdim];
__device__ f16 g_at  [Mrows * Hdim];
__device__ f16 g_xbh [Mrows * Hdim];
__device__ f16 g_qkv [Mrows * 3 * Hdim];
__device__ f16 g_kv  [Crows * KVW];
__device__ f16 g_hid [Mrows * MlpD];
__device__ f16 g_c   [Crows * CtxD];
__device__ f16 g_wqkv[3 * Hdim * Hdim];
__device__ f16 g_wpr [Hdim * Hdim];
__device__ f16 g_wq  [Hdim * Hdim];
__device__ f16 g_wkv [KVW * CtxD];
__device__ f16 g_wo  [Hdim * Hdim];
__device__ f16 g_w1  [MlpD * Hdim];
__device__ f16 g_w2  [Hdim * MlpD];

// ------------------------------ helpers ------------------------------------
__device__ __forceinline__ float ex2(float x) {
  float y; asm("ex2.approx.f32 %0, %1;" : "=f"(y) : "f"(x)); return y;
}
__device__ __forceinline__ uint32_t pack_f16x2(float lo, float hi) {
  uint32_t d;
  asm("cvt.rn.f16x2.f32 %0, %1, %2;" : "=r"(d) : "f"(hi), "f"(lo));
  return d;
}

// -------------------- fused weight/context conversion ----------------------
struct CvtJobs {
  const float* src[9];
  f16* dst[9];
  int n[9];
};

__global__ __launch_bounds__(256) void cvt_all_kernel(CvtJobs J) {
  int t = blockIdx.y;
  int i = (blockIdx.x * 256 + threadIdx.x) * 4;
  if (i >= J.n[t]) return;
  float4 v = *(const float4*)(J.src[t] + i);
  f16* d = J.dst[t];
  *(f162*)(d + i)     = __floats2half2_rn(v.x, v.y);
  *(f162*)(d + i + 2) = __floats2half2_rn(v.z, v.w);
}

// --------------------------- adaLN modulation ------------------------------
__global__ __launch_bounds__(128) void ada_kernel(
    const float* __restrict__ t_emb, const float* __restrict__ ada_w,
    const float* __restrict__ ada_b, float* __restrict__ mod) {
  __shared__ float se[Bsz * Hdim];
  int tid = threadIdx.x;
  for (int i = tid; i < Bsz * Hdim; i += 128) {
    float v = t_emb[i];
    se[i] = v / (1.f + __expf(-v));
  }
  __syncthreads();
  int j = blockIdx.x * 128 + tid;
  const float* w = ada_w + (size_t)j * Hdim;
  float acc[Bsz];
#pragma unroll
  for (int b = 0; b < Bsz; b++) acc[b] = 0.f;
  for (int k = 0; k < Hdim; k += 4) {
    float4 wv = *(const float4*)(w + k);
#pragma unroll
    for (int b = 0; b < Bsz; b++) {
      const float* s = se + b * Hdim + k;
      acc[b] += wv.x * s[0] + wv.y * s[1] + wv.z * s[2] + wv.w * s[3];
    }
  }
  float bb = ada_b[j];
#pragma unroll
  for (int b = 0; b < Bsz; b++) mod[b * ModW + j] = acc[b] + bb;
}

// ----------------- LayerNorm + modulate -> fp16 (vectorized) ---------------
// 288 float4 per row: thread t loads float4 #t, threads 0..31 also #(t+256).
__global__ __launch_bounds__(256) void ln_mod_kernel(
    const float* __restrict__ x, const float* __restrict__ mod,
    int sh_off, int sc_off, f16* __restrict__ o16) {
  int row = blockIdx.x;
  int b = row >> 10;
  int tid = threadIdx.x;
  const float4* xr4 = (const float4*)(x + (size_t)row * Hdim);

  float4 v0 = xr4[tid];
  float4 v1 = make_float4(0.f, 0.f, 0.f, 0.f);
  bool has2 = tid < 32;
  if (has2) v1 = xr4[tid + 256];

  float s  = v0.x + v0.y + v0.z + v0.w;
  float ss = v0.x * v0.x + v0.y * v0.y + v0.z * v0.z + v0.w * v0.w;
  if (has2) {
    s  += v1.x + v1.y + v1.z + v1.w;
    ss += v1.x * v1.x + v1.y * v1.y + v1.z * v1.z + v1.w * v1.w;
  }
#pragma unroll
  for (int o = 16; o > 0; o >>= 1) {
    s  += __shfl_xor_sync(0xffffffffu, s, o);
    ss += __shfl_xor_sync(0xffffffffu, ss, o);
  }
  __shared__ float rs[8], rss[8], stat[2];
  int w = tid >> 5;
  if ((tid & 31) == 0) { rs[w] = s; rss[w] = ss; }
  __syncthreads();
  if (tid == 0) {
    float S = 0.f, SS = 0.f;
#pragma unroll
    for (int i = 0; i < 8; i++) { S += rs[i]; SS += rss[i]; }
    float mu = S * (1.f / Hdim);
    float var = SS * (1.f / Hdim) - mu * mu;
    stat[0] = mu;
    stat[1] = rsqrtf(var + 1e-6f);
  }
  __syncthreads();
  float mu = stat[0], rstd = stat[1];

  const float4* sh4 = (const float4*)(mod + b * ModW + sh_off * Hdim);
  const float4* sc4 = (const float4*)(mod + b * ModW + sc_off * Hdim);
  f16* o = o16 + (size_t)row * Hdim;

  {
    float4 sh = sh4[tid], sc = sc4[tid];
    float r0 = (v0.x - mu) * rstd * (1.f + sc.x) + sh.x;
    float r1 = (v0.y - mu) * rstd * (1.f + sc.y) + sh.y;
    float r2 = (v0.z - mu) * rstd * (1.f + sc.z) + sh.z;
    float r3 = (v0.w - mu) * rstd * (1.f + sc.w) + sh.w;
    uint2 pk;
    pk.x = pack_f16x2(r0, r1);
    pk.y = pack_f16x2(r2, r3);
    *(uint2*)(o + tid * 4) = pk;
  }
  if (has2) {
    float4 sh = sh4[tid + 256], sc = sc4[tid + 256];
    float r0 = (v1.x - mu) * rstd * (1.f + sc.x) + sh.x;
    float r1 = (v1.y - mu) * rstd * (1.f + sc.y) + sh.y;
    float r2 = (v1.z - mu) * rstd * (1.f + sc.z) + sh.z;
    float r3 = (v1.w - mu) * rstd * (1.f + sc.w) + sh.w;
    uint2 pk;
    pk.x = pack_f16x2(r0, r1);
    pk.y = pack_f16x2(r2, r3);
    *(uint2*)(o + (tid + 256) * 4) = pk;
  }
}

// ------------------- tensor-core GEMM (NT, fp16) ----------------------------
__device__ __forceinline__ float gelu_tanh(float v) {
  const float c = 0.7978845608028654f;
  return 0.5f * v * (1.f + tanhf(c * (v + 0.044715f * v * v * v)));
}

#define EPI_BIAS    0
#define EPI_GELU    1
#define EPI_RESGATE 2

__device__ __forceinline__ void mma_f16(float c[4], const uint32_t a[4],
                                        const uint32_t b[2]) {
  asm volatile(
      "mma.sync.aligned.m16n8k16.row.col.f32.f16.f16.f32 "
      "{%0,%1,%2,%3}, {%4,%5,%6,%7}, {%8,%9}, {%0,%1,%2,%3};"
      : "+f"(c[0]), "+f"(c[1]), "+f"(c[2]), "+f"(c[3])
      : "r"(a[0]), "r"(a[1]), "r"(a[2]), "r"(a[3]), "r"(b[0]), "r"(b[1]));
}
__device__ __forceinline__ void mma_f16_k8(float c[4], const uint32_t a[2],
                                           uint32_t b0) {
  asm volatile(
      "mma.sync.aligned.m16n8k8.row.col.f32.f16.f16.f32 "
      "{%0,%1,%2,%3}, {%4,%5}, {%6}, {%0,%1,%2,%3};"
      : "+f"(c[0]), "+f"(c[1]), "+f"(c[2]), "+f"(c[3])
      : "r"(a[0]), "r"(a[1]), "r"(b0));
}

__device__ __forceinline__ void ldsm4(uint32_t r[4], uint32_t addr) {
  asm volatile("ldmatrix.sync.aligned.m8n8.x4.shared.b16 {%0,%1,%2,%3}, [%4];"
               : "=r"(r[0]), "=r"(r[1]), "=r"(r[2]), "=r"(r[3]) : "r"(addr));
}
__device__ __forceinline__ void ldsm4t(uint32_t r[4], uint32_t addr) {
  asm volatile(
      "ldmatrix.sync.aligned.m8n8.x4.trans.shared.b16 {%0,%1,%2,%3}, [%4];"
      : "=r"(r[0]), "=r"(r[1]), "=r"(r[2]), "=r"(r[3]) : "r"(addr));
}

__device__ __forceinline__ void cp16(uint32_t dst, const void* src, bool p) {
  int sz = p ? 16 : 0;
  asm volatile("cp.async.cg.shared.global [%0], [%1], 16, %2;\n"
               :: "r"(dst), "l"(src), "r"(sz));
}

// K-tile 64: plane = 128 rows x 144B (128B data + 16B pad). 2 stages.
#define PL_B    18432
#define STAGE_B (2 * PL_B)       // A, B = 36864
#define GSMEM   (2 * STAGE_B)    // 73728

template <int EPI, bool OUTF, bool OUTB>
__global__ __launch_bounds__(256, 2) void gemm_tc(
    const f16* __restrict__ A, const f16* __restrict__ W,
    const float* __restrict__ bias, const float* __restrict__ res,
    const float* __restrict__ gate, float* __restrict__ C,
    f16* __restrict__ C16,
    int M, int N, int K) {
  extern __shared__ char smc[];
  uint32_t sbase = (uint32_t)__cvta_generic_to_shared(smc);
  int tid = threadIdx.x;
  int warp = tid >> 5, lane = tid & 31;
  int wm = warp & 3, wn = warp >> 2;     // 4 warps M x 2 warps N
  int m0 = blockIdx.y << 7, n0 = blockIdx.x << 7;

  float acc[2][8][4];
#pragma unroll
  for (int mt = 0; mt < 2; mt++)
#pragma unroll
    for (int nt = 0; nt < 8; nt++)
#pragma unroll
      for (int f = 0; f < 4; f++) acc[mt][nt][f] = 0.f;

  int lq = lane & 7, lb = (lane >> 3) & 1, lh = lane >> 4;
  uint32_t offA[2], offB[4];
#pragma unroll
  for (int mt = 0; mt < 2; mt++)
    offA[mt] = (uint32_t)((wm * 32 + mt * 16 + lq + lb * 8) * 144 + lh * 16);
#pragma unroll
  for (int j = 0; j < 4; j++)
    offB[j] = (uint32_t)(PL_B +
                         (wn * 64 + j * 16 + lq + lh * 8) * 144 + lb * 16);

  const int nk = K >> 6;

  auto issue = [&](int kt, int s) {
    uint32_t st = sbase + s * STAGE_B;
    int k0 = kt << 6;
#pragma unroll
    for (int i = 0; i < 8; i++) {
      int idx = tid + (i << 8);
      int pl = idx >> 10;          // 0=A, 1=B
      int cc = idx & 1023;
      int row = cc >> 3, ch = cc & 7;
      uint32_t d = st + pl * PL_B + row * 144 + ch * 16;
      const f16* src;
      bool ok = true;
      if (pl == 0) {
        int gm = m0 + row;
        ok = gm < M;
        src = A + (size_t)(ok ? gm : 0) * K + k0 + ch * 8;
      } else {
        src = W + (size_t)(n0 + row) * K + k0 + ch * 8;
      }
      cp16(d, src, ok);
    }
    asm volatile("cp.async.commit_group;\n");
  };

  issue(0, 0);
  for (int kt = 0; kt < nk; kt++) {
    int s = kt & 1;
    if (kt + 1 < nk) {
      issue(kt + 1, s ^ 1);
      asm volatile("cp.async.wait_group 1;\n");
    } else {
      asm volatile("cp.async.wait_group 0;\n");
    }
    __syncthreads();

    uint32_t sb = sbase + s * STAGE_B;
#pragma unroll
    for (int ks = 0; ks < 4; ks++) {
      uint32_t a_[2][4];
#pragma unroll
      for (int mt = 0; mt < 2; mt++)
        ldsm4(a_[mt], sb + offA[mt] + ks * 32);
#pragma unroll
      for (int jp = 0; jp < 2; jp++) {
        uint32_t b0[4], b1[4];
        ldsm4(b0, sb + offB[2 * jp]     + ks * 32);
        ldsm4(b1, sb + offB[2 * jp + 1] + ks * 32);
        float (*a0)[4] = acc[0], (*a1)[4] = acc[1];
        int q = 4 * jp;
        mma_f16(a0[q],     a_[0], b0);
        mma_f16(a0[q + 1], a_[0], b0 + 2);
        mma_f16(a1[q],     a_[1], b0);
        mma_f16(a1[q + 1], a_[1], b0 + 2);
        mma_f16(a0[q + 2], a_[0], b1);
        mma_f16(a0[q + 3], a_[0], b1 + 2);
        mma_f16(a1[q + 2], a_[1], b1);
        mma_f16(a1[q + 3], a_[1], b1 + 2);
      }
    }
    __syncthreads();
  }

  int g = lane >> 2, tg = lane & 3;
#pragma unroll
  for (int mt = 0; mt < 2; mt++) {
#pragma unroll
    for (int half = 0; half < 2; half++) {
      int m = m0 + wm * 32 + mt * 16 + g + half * 8;
      if (m >= M) continue;
      int bq = m >> 10;
#pragma unroll
      for (int nt = 0; nt < 8; nt++) {
        int n = n0 + wn * 64 + nt * 8 + tg * 2;
        float v0 = acc[mt][nt][half * 2 + 0];
        float v1 = acc[mt][nt][half * 2 + 1];
        if (bias) { v0 += bias[n]; v1 += bias[n + 1]; }
        if (EPI == EPI_GELU) { v0 = gelu_tanh(v0); v1 = gelu_tanh(v1); }
        if (EPI == EPI_RESGATE) {
          float g0 = 1.f, g1 = 1.f;
          if (gate) { g0 = gate[bq * ModW + n]; g1 = gate[bq * ModW + n + 1]; }
          v0 = res[(size_t)m * N + n] + g0 * v0;
          v1 = res[(size_t)m * N + n + 1] + g1 * v1;
        }
        if (OUTF)
          *(float2*)(C + (size_t)m * N + n) = make_float2(v0, v1);
        if (OUTB)
          *(f162*)(C16 + (size_t)m * N + n) = __floats2half2_rn(v0, v1);
      }
    }
  }
}

// ---------------- tensor-core flash attention (fp16) ------------------------
// Templated on KV tile width: 128 for self-attn, 80 for cross-attn (kv=77).
#define ARB   176
#define APL   (128 * ARB)
#define ATSM  (5 * APL)            // Q + 2 stages x (K,V)

template <int KVT>
__global__ __launch_bounds__(256) void attn_tc(
    const f16* __restrict__ Q, long long qbs, int ldq,
    const f16* __restrict__ Kp, const f16* __restrict__ Vp,
    long long kbs, int ldk,
    f16* __restrict__ O,
    int kv_len, float sl2e) {
  constexpr int NT16 = KVT / 16;
  constexpr int NJ   = KVT / 8;
  constexpr int KC   = KVT / 16;
  extern __shared__ char smb[];
  uint32_t sb = (uint32_t)__cvta_generic_to_shared(smb);
  int b = blockIdx.z, h = blockIdx.y;
  int m0 = blockIdx.x * 128;
  int tid = threadIdx.x, warp = tid >> 5, lane = tid & 31;
  int g = lane >> 2, tg = lane & 3;
  int lq = lane & 7, lb = (lane >> 3) & 1, lh = lane >> 4;

  const f16* Qb = Q  + (size_t)b * qbs + (size_t)m0 * ldq + h * HeadD;
  const f16* Kb = Kp + (size_t)b * kbs + h * HeadD;
  const f16* Vb = Vp + (size_t)b * kbs + h * HeadD;

  for (int i = tid; i < 640; i += 256) {
    int p = i >> 7, r = i & 127;
    uint32_t ad = sb + p * APL + r * ARB + 144;
    asm volatile("st.shared.v4.b32 [%0], {%1,%1,%1,%1};" :: "r"(ad), "r"(0));
    asm volatile("st.shared.v4.b32 [%0], {%1,%1,%1,%1};"
                 :: "r"(ad + 16), "r"(0));
  }

  for (int i = tid; i < 1152; i += 256) {
    int r = i / 9, ch = i % 9;
    cp16(sb + r * ARB + ch * 16, Qb + (size_t)r * ldq + ch * 8, true);
  }

  auto loadKV = [&](int j0, int s) {
    uint32_t st = sb + APL + s * 2 * APL;
    for (int i = tid; i < KVT * 9; i += 256) {
      int r = i / 9, ch = i % 9;
      bool ok = (j0 + r) < kv_len;
      int rc = ok ? (j0 + r) : 0;
      size_t off = (size_t)rc * ldk + ch * 8;
      uint32_t d = st + r * ARB + ch * 16;
      cp16(d,       Kb + off, ok);
      cp16(d + APL, Vb + off, ok);
    }
    asm volatile("cp.async.commit_group;\n");
  };

  int iters = (kv_len + KVT - 1) / KVT;
  loadKV(0, 0);
  if (iters > 1) loadKV(KVT, 1);

  float m0r = -1e30f, m1r = -1e30f, ls0 = 0.f, ls1 = 0.f;
  float oacc[9][4];
#pragma unroll
  for (int nt = 0; nt < 9; nt++)
#pragma unroll
    for (int f = 0; f < 4; f++) oacc[nt][f] = 0.f;

  uint32_t offA = (uint32_t)((warp * 16 + lq + lb * 8) * ARB + lh * 16);
  uint32_t offB = (uint32_t)((lq + lh * 8) * ARB + lb * 16);
  uint32_t offV = (uint32_t)((lq + lb * 8) * ARB + lh * 16);

  for (int it = 0; it < iters; it++) {
    if (it + 1 < iters) {
      if (it > 0) loadKV((it + 1) * KVT, (it + 1) & 1);
      asm volatile("cp.async.wait_group 1;\n");
    } else {
      asm volatile("cp.async.wait_group 0;\n");
    }
    __syncthreads();

    uint32_t kbse = sb + APL + (it & 1) * 2 * APL;

    float sa[NJ][4];
#pragma unroll
    for (int j = 0; j < NJ; j++)
#pragma unroll
      for (int f = 0; f < 4; f++) sa[j][f] = 0.f;

#pragma unroll
    for (int ks = 0; ks < 4; ks++) {
      uint32_t a_[4];
      ldsm4(a_, sb + offA + ks * 32);
#pragma unroll
      for (int nt = 0; nt < NT16; nt++) {
        uint32_t bb[4];
        ldsm4(bb, kbse + offB + nt * 16 * ARB + ks * 32);
        mma_f16(sa[2 * nt],     a_, bb);
        mma_f16(sa[2 * nt + 1], a_, bb + 2);
      }
    }
    {
      uint32_t a_[4];
      ldsm4(a_, sb + offA + 4 * 32);
#pragma unroll
      for (int nt = 0; nt < NT16; nt++) {
        uint32_t bb[4];
        ldsm4(bb, kbse + offB + nt * 16 * ARB + 4 * 32);
        mma_f16_k8(sa[2 * nt],     a_, bb[0]);
        mma_f16_k8(sa[2 * nt + 1], a_, bb[2]);
      }
    }

    int j0 = it * KVT;
    bool msk = (j0 + KVT) > kv_len;
    float mx0 = -1e30f, mx1 = -1e30f;
#pragma unroll
    for (int j = 0; j < NJ; j++) {
#pragma unroll
      for (int e = 0; e < 4; e++) {
        float v = sa[j][e] * sl2e;
        if (msk) {
          int col = j * 8 + 2 * tg + (e & 1);
          if (j0 + col >= kv_len) v = -1e30f;
        }
        sa[j][e] = v;
      }
      mx0 = fmaxf(mx0, fmaxf(sa[j][0], sa[j][1]));
      mx1 = fmaxf(mx1, fmaxf(sa[j][2], sa[j][3]));
    }
    mx0 = fmaxf(mx0, __shfl_xor_sync(0xffffffffu, mx0, 1));
    mx0 = fmaxf(mx0, __shfl_xor_sync(0xffffffffu, mx0, 2));
    mx1 = fmaxf(mx1, __shfl_xor_sync(0xffffffffu, mx1, 1));
    mx1 = fmaxf(mx1, __shfl_xor_sync(0xffffffffu, mx1, 2));
    float mn0 = fmaxf(m0r, mx0), mn1 = fmaxf(m1r, mx1);
    float al0 = ex2(m0r - mn0), al1 = ex2(m1r - mn1);
    m0r = mn0; m1r = mn1;

    float s0 = 0.f, s1 = 0.f;
#pragma unroll
    for (int j = 0; j < NJ; j++) {
      float p0 = ex2(sa[j][0] - mn0), p1 = ex2(sa[j][1] - mn0);
      float p2 = ex2(sa[j][2] - mn1), p3 = ex2(sa[j][3] - mn1);
      sa[j][0] = p0; sa[j][1] = p1; sa[j][2] = p2; sa[j][3] = p3;
      s0 += p0 + p1; s1 += p2 + p3;
    }
    s0 += __shfl_xor_sync(0xffffffffu, s0, 1);
    s0 += __shfl_xor_sync(0xffffffffu, s0, 2);
    s1 += __shfl_xor_sync(0xffffffffu, s1, 1);
    s1 += __shfl_xor_sync(0xffffffffu, s1, 2);
    ls0 = ls0 * al0 + s0;
    ls1 = ls1 * al1 + s1;
#pragma unroll
    for (int nt = 0; nt < 9; nt++) {
      oacc[nt][0] *= al0; oacc[nt][1] *= al0;
      oacc[nt][2] *= al1; oacc[nt][3] *= al1;
    }

    uint32_t vbse = kbse + APL;
#pragma unroll
    for (int kc = 0; kc < KC; kc++) {
      uint32_t pa[4];
      pa[0] = pack_f16x2(sa[2 * kc][0],     sa[2 * kc][1]);
      pa[1] = pack_f16x2(sa[2 * kc][2],     sa[2 * kc][3]);
      pa[2] = pack_f16x2(sa[2 * kc + 1][0], sa[2 * kc + 1][1]);
      pa[3] = pack_f16x2(sa[2 * kc + 1][2], sa[2 * kc + 1][3]);
#pragma unroll
      for (int npp = 0; npp < 2; npp++) {
        int np0 = 2 * npp, np1 = 2 * npp + 1;
        uint32_t v0[4], v1[4];
        ldsm4t(v0, vbse + offV + kc * 16 * ARB + np0 * 32);
        ldsm4t(v1, vbse + offV + kc * 16 * ARB + np1 * 32);
        mma_f16(oacc[2 * np0],     pa, v0);
        mma_f16(oacc[2 * np0 + 1], pa, v0 + 2);
        mma_f16(oacc[2 * np1],     pa, v1);
        mma_f16(oacc[2 * np1 + 1], pa, v1 + 2);
      }
      {
        uint32_t v4[4];
        ldsm4t(v4, vbse + offV + kc * 16 * ARB + 4 * 32);
        mma_f16(oacc[8], pa, v4);
      }
    }
    __syncthreads();
  }

  float inv0 = 1.f / ls0, inv1 = 1.f / ls1;
  int r0 = m0 + warp * 16 + g, r1 = r0 + 8;
  size_t base0 = ((size_t)b * Ntok + r0) * Hdim + h * HeadD;
  size_t base1 = ((size_t)b * Ntok + r1) * Hdim + h * HeadD;
#pragma unroll
  for (int nt = 0; nt < 9; nt++) {
    int col = nt * 8 + 2 * tg;
    *(f162*)(O + base0 + col) =
        __floats2half2_rn(oacc[nt][0] * inv0, oacc[nt][1] * inv0);
    *(f162*)(O + base1 + col) =
        __floats2half2_rn(oacc[nt][2] * inv1, oacc[nt][3] * inv1);
  }
}

// ------------------------------ launcher -----------------------------------
static float* sym_f(const void* s) { void* p; cudaGetSymbolAddress(&p, s); return (float*)p; }
static f16*   sym_h(const void* s) { void* p; cudaGetSymbolAddress(&p, s); return (f16*)p; }

extern "C" void kernel_launch(void* const* d_in, const int* in_sizes, int n_in,
                              void* d_out, int out_size) {
  (void)in_sizes; (void)n_in; (void)out_size;
  const float* x        = (const float*)d_in[0];
  const float* c        = (const float*)d_in[1];
  const float* t_emb    = (const float*)d_in[2];
  const float* qkv_w    = (const float*)d_in[3];
  const float* qkv_b    = (const float*)d_in[4];
  const float* proj_w   = (const float*)d_in[5];
  const float* proj_b   = (const float*)d_in[6];
  const float* to_q_w   = (const float*)d_in[7];
  const float* to_k_w   = (const float*)d_in[8];
  const float* to_v_w   = (const float*)d_in[9];
  const float* to_out_w = (const float*)d_in[10];
  const float* to_out_b = (const float*)d_in[11];
  const float* mlp_w1   = (const float*)d_in[12];
  const float* mlp_b1   = (const float*)d_in[13];
  const float* mlp_w2   = (const float*)d_in[14];
  const float* mlp_b2   = (const float*)d_in[15];
  const float* ada_w    = (const float*)d_in[16];
  const float* ada_b    = (const float*)d_in[17];
  float* out = (float*)d_out;

  float *mod = sym_f(&g_mod), *xb = sym_f(&g_xb);
  f16 *ln = sym_h(&g_ln), *at = sym_h(&g_at), *xbh = sym_h(&g_xbh);
  f16 *qkv = sym_h(&g_qkv), *kv = sym_h(&g_kv), *hid = sym_h(&g_hid);
  f16 *cc = sym_h(&g_c);
  f16 *wqkv = sym_h(&g_wqkv), *wpr = sym_h(&g_wpr), *wq = sym_h(&g_wq);
  f16 *wkv = sym_h(&g_wkv), *wo = sym_h(&g_wo);
  f16 *w1 = sym_h(&g_w1), *w2 = sym_h(&g_w2);

  cudaFuncSetAttribute(attn_tc<128>,
                       cudaFuncAttributeMaxDynamicSharedMemorySize, ATSM);
  cudaFuncSetAttribute(attn_tc<80>,
                       cudaFuncAttributeMaxDynamicSharedMemorySize, ATSM);
#define SETSM(k) cudaFuncSetAttribute(k, \
    cudaFuncAttributeMaxDynamicSharedMemorySize, GSMEM)
  SETSM((gemm_tc<EPI_BIAS, false, true>));
  SETSM((gemm_tc<EPI_GELU, false, true>));
  SETSM((gemm_tc<EPI_RESGATE, true, true>));
  SETSM((gemm_tc<EPI_RESGATE, true, false>));
#undef SETSM

  const float sl2e = (1.f / sqrtf((float)HeadD)) * 1.4426950408889634f;

  // side stream + fork/join events (host objects only; no device memory).
  cudaStream_t s2;
  cudaStreamCreateWithFlags(&s2, cudaStreamNonBlocking);
  cudaEvent_t evRoot, evCvt, evJoin;
  cudaEventCreateWithFlags(&evRoot, cudaEventDisableTiming);
  cudaEventCreateWithFlags(&evCvt,  cudaEventDisableTiming);
  cudaEventCreateWithFlags(&evJoin, cudaEventDisableTiming);

  cudaEventRecord(evRoot, 0);
  cudaStreamWaitEvent(s2, evRoot, 0);

  // s2 branch: conversions -> cross-attn K|V GEMM
  {
    CvtJobs J;
    const float* s[9] = {qkv_w, proj_w, to_q_w, to_k_w, to_v_w,
                         to_out_w, mlp_w1, mlp_w2, c};
    f16* dd[9] = {wqkv, wpr, wq, wkv, wkv + Hdim * CtxD, wo, w1, w2, cc};
    int nn[9] = {3 * Hdim * Hdim, Hdim * Hdim, Hdim * Hdim, Hdim * CtxD,
                 Hdim * CtxD, Hdim * Hdim, MlpD * Hdim, Hdim * MlpD,
                 Crows * CtxD};
    for (int i = 0; i < 9; i++) { J.src[i] = s[i]; J.dst[i] = dd[i];
                                  J.n[i] = nn[i]; }
    dim3 g((MlpD * Hdim / 4 + 255) / 256, 9);
    cvt_all_kernel<<<g, 256, 0, s2>>>(J);
    cudaEventRecord(evCvt, s2);
    dim3 gkv(KVW / 128, (Crows + 127) / 128);
    gemm_tc<EPI_BIAS, false, true><<<gkv, 256, GSMEM, s2>>>(
        cc, wkv, nullptr, nullptr, nullptr,
        nullptr, kv, Crows, KVW, CtxD);
    cudaEventRecord(evJoin, s2);
  }

  // main branch: ada + ln overlap cvt
  ada_kernel<<<ModW / 128, 128>>>(t_emb, ada_w, ada_b, mod);
  ln_mod_kernel<<<Mrows, 256>>>(x, mod, 0, 1, ln);
  cudaStreamWaitEvent(0, evCvt, 0);
  // qkv
  {
    dim3 g(3 * Hdim / 128, Mrows / 128);
    gemm_tc<EPI_BIAS, false, true><<<g, 256, GSMEM>>>(
        ln, wqkv, qkv_b, nullptr, nullptr,
        nullptr, qkv, Mrows, 3 * Hdim, Hdim);
  }
  // self-attention (KV tile 128)
  {
    dim3 g(Ntok / 128, NHead, Bsz);
    attn_tc<128><<<g, 256, ATSM>>>(
        qkv, (long long)Ntok * 3 * Hdim, 3 * Hdim,
        qkv + Hdim, qkv + 2 * Hdim, (long long)Ntok * 3 * Hdim, 3 * Hdim,
        at, Ntok, sl2e);
  }
  // proj + gated residual; cross-attn Q
  {
    dim3 g(Hdim / 128, Mrows / 128);
    gemm_tc<EPI_RESGATE, true, true><<<g, 256, GSMEM>>>(
        at, wpr, proj_b, x, mod + 2 * Hdim,
        xb, xbh, Mrows, Hdim, Hdim);
    gemm_tc<EPI_BIAS, false, true><<<g, 256, GSMEM>>>(
        xbh, wq, nullptr, nullptr, nullptr,
        nullptr, ln, Mrows, Hdim, Hdim);
  }
  // join: kv ready before cross-attention
  cudaStreamWaitEvent(0, evJoin, 0);
  // cross-attention (KV tile 80)
  {
    dim3 g(Ntok / 128, NHead, Bsz);
    attn_tc<80><<<g, 256, ATSM>>>(
        ln, (long long)Ntok * Hdim, Hdim,
        kv, kv + Hdim, (long long)CtxT * KVW, KVW,
        at, CtxT, sl2e);
  }
  // to_out + residual
  {
    dim3 g(Hdim / 128, Mrows / 128);
    gemm_tc<EPI_RESGATE, true, false><<<g, 256, GSMEM>>>(
        at, wo, to_out_b, xb, nullptr,
        xb, nullptr, Mrows, Hdim, Hdim);
  }
  ln_mod_kernel<<<Mrows, 256>>>(xb, mod, 3, 4, ln);
  // MLP
  {
    dim3 g1(MlpD / 128, Mrows / 128);
    gemm_tc<EPI_GELU, false, true><<<g1, 256, GSMEM>>>(
        ln, w1, mlp_b1, nullptr, nullptr,
        nullptr, hid, Mrows, MlpD, Hdim);
    dim3 g2(Hdim / 128, Mrows / 128);
    gemm_tc<EPI_RESGATE, true, false><<<g2, 256, GSMEM>>>(
        hid, w2, mlp_b2, xb, mod + 5 * Hdim,
        out, nullptr, Mrows, Hdim, MlpD);
  }
  // stream/events intentionally not destroyed (capture-safe; host-only).
}